// round 3
// baseline (speedup 1.0000x reference)
#include <cuda_runtime.h>

// Tiny-ViT fully fused forward, round 2 (resubmit — previous bench hit an
// infra container failure, not a kernel failure).
// Mapping: 64 threads own tokens of TWO images (register-blocked over batch):
//   - every weight row loaded from shared feeds both images (halves weight LDS/img)
//   - one-pass online softmax (no score recompute; no max pre-pass)
//   - K/V of a token packed in one 64B shared row -> 4x LDS.128 per (u, image)
// CTA: 256 threads = 4 slots x 64 threads, 8 images per CTA.

namespace {
constexpr int NB   = 4;    // transformer blocks
constexpr int TT   = 50;   // tokens
constexpr int NTH  = 256;
constexpr int IPC  = 8;    // images per CTA

struct SW {
  float linW[128];          // [8][16]
  float cls[8];
  float pos[TT * 8];
  float ln1g[NB * 8], ln1b[NB * 8];
  float Wq[NB * 64], Wk[NB * 64], Wv[NB * 64];
  float projW[NB * 64], projb[NB * 8];
  float ln2g[NB * 8], ln2b[NB * 8];
  float W1[NB * 256], b1[NB * 32];  // W1 [32][8]
  float W2t[NB * 256], b2[NB * 8];  // W2 transposed -> [32][8]
  float mlpW[80], mlpb[12];
};
}  // namespace

// dot8 of two register vectors against one shared row (row loaded once).
__device__ __forceinline__ void dot8_2(const float* __restrict__ w,
                                       const float a[8], const float b[8],
                                       float& ra, float& rb) {
  float4 w0 = *reinterpret_cast<const float4*>(w);
  float4 w1 = *reinterpret_cast<const float4*>(w + 4);
  ra = fmaf(a[0], w0.x, fmaf(a[1], w0.y, fmaf(a[2], w0.z, fmaf(a[3], w0.w,
       fmaf(a[4], w1.x, fmaf(a[5], w1.y, fmaf(a[6], w1.z, a[7] * w1.w)))))));
  rb = fmaf(b[0], w0.x, fmaf(b[1], w0.y, fmaf(b[2], w0.z, fmaf(b[3], w0.w,
       fmaf(b[4], w1.x, fmaf(b[5], w1.y, fmaf(b[6], w1.z, b[7] * w1.w)))))));
}

__device__ __forceinline__ void layernorm(const float x[8],
                                          const float* __restrict__ g,
                                          const float* __restrict__ b,
                                          float h[8]) {
  float mu = 0.f;
#pragma unroll
  for (int d = 0; d < 8; d++) mu += x[d];
  mu *= 0.125f;
  float var = 0.f;
#pragma unroll
  for (int d = 0; d < 8; d++) { float c = x[d] - mu; var = fmaf(c, c, var); }
  float rs = rsqrtf(var * 0.125f + 1e-5f);
#pragma unroll
  for (int d = 0; d < 8; d++) h[d] = (x[d] - mu) * rs * g[d] + b[d];
}

struct OS { float m, l; float4 a; };

__device__ __forceinline__ void os_init(OS& s) {
  s.m = -1e30f; s.l = 0.f; s.a = make_float4(0.f, 0.f, 0.f, 0.f);
}

__device__ __forceinline__ void os_upd(OS& s, const float4 q, const float4 k,
                                       const float4 v) {
  float sc = fmaf(q.x, k.x, fmaf(q.y, k.y, fmaf(q.z, k.z, q.w * k.w)));
  if (sc > s.m) {  // rare after warmup; predicated short arm
    float c = __expf(s.m - sc);
    s.l *= c; s.a.x *= c; s.a.y *= c; s.a.z *= c; s.a.w *= c;
    s.m = sc;
  }
  float p = __expf(sc - s.m);
  s.l += p;
  s.a.x = fmaf(p, v.x, s.a.x); s.a.y = fmaf(p, v.y, s.a.y);
  s.a.z = fmaf(p, v.z, s.a.z); s.a.w = fmaf(p, v.w, s.a.w);
}

__global__ void __launch_bounds__(NTH) vit_kernel(
    const float* __restrict__ images, const float* __restrict__ cls_g,
    const float* __restrict__ linW_g, const float* __restrict__ ln1g_g,
    const float* __restrict__ ln1b_g, const float* __restrict__ Wq_g,
    const float* __restrict__ Wk_g, const float* __restrict__ Wv_g,
    const float* __restrict__ projW_g, const float* __restrict__ projb_g,
    const float* __restrict__ ln2g_g, const float* __restrict__ ln2b_g,
    const float* __restrict__ W1_g, const float* __restrict__ b1_g,
    const float* __restrict__ W2_g, const float* __restrict__ b2_g,
    const float* __restrict__ mlpW_g, const float* __restrict__ mlpb_g,
    float* __restrict__ out, int B) {
  __shared__ __align__(16) SW sw;
  // K/V packed per token: [k0..k7, v0..v7] = 64B rows
  __shared__ __align__(16) float skv[IPC][TT * 16];

  const int tid = threadIdx.x;

  // ---- stage weights into shared ----
  {
    auto cp = [&](float* d, const float* s, int n) {
      for (int i = tid; i < n; i += NTH) d[i] = s[i];
    };
    cp(sw.linW, linW_g, 128);
    cp(sw.cls, cls_g, 8);
    cp(sw.ln1g, ln1g_g, 32);  cp(sw.ln1b, ln1b_g, 32);
    cp(sw.Wq, Wq_g, 256);     cp(sw.Wk, Wk_g, 256);   cp(sw.Wv, Wv_g, 256);
    cp(sw.projW, projW_g, 256); cp(sw.projb, projb_g, 32);
    cp(sw.ln2g, ln2g_g, 32);  cp(sw.ln2b, ln2b_g, 32);
    cp(sw.W1, W1_g, 1024);    cp(sw.b1, b1_g, 128);
    cp(sw.b2, b2_g, 32);
    cp(sw.mlpW, mlpW_g, 80);
    for (int i = tid; i < 10; i += NTH) sw.mlpb[i] = mlpb_g[i];
    // W2 [blk][8][32] -> transposed [blk][32][8]
    for (int i = tid; i < NB * 256; i += NTH) {
      int blk = i >> 8, rem = i & 255, f = rem >> 3, d = rem & 7;
      sw.W2t[blk * 256 + rem] = W2_g[blk * 256 + d * 32 + f];
    }
    // sinusoidal positional table: 10000^(j/8) -> freqs {1, .1, .01, .001}
    if (tid < TT) {
      float tf = (float)tid;
      float* p = sw.pos + tid * 8;
      p[0] = sinf(tf);           p[1] = cosf(tf);
      p[2] = sinf(tf * 0.1f);    p[3] = cosf(tf * 0.1f);
      p[4] = sinf(tf * 0.01f);   p[5] = cosf(tf * 0.01f);
      p[6] = sinf(tf * 0.001f);  p[7] = cosf(tf * 0.001f);
    }
  }
  __syncthreads();

  const int slot = tid >> 6;   // 0..3
  const int t    = tid & 63;   // token id
  const int gb0  = blockIdx.x * IPC + slot * 2;
  const int gb1  = gb0 + 1;
  const bool tok = (t < TT);
  const bool a0  = tok && (gb0 < B);
  const bool a1  = tok && (gb1 < B);

  float xA[8], xB[8];
#pragma unroll
  for (int d = 0; d < 8; d++) { xA[d] = 0.f; xB[d] = 0.f; }

  // ---- patch embed + positional ----
  auto embed = [&](int gb, float x[8]) {
    if (t == 0) {
#pragma unroll
      for (int d = 0; d < 8; d++) x[d] = sw.cls[d] + sw.pos[d];
    } else {
      int p = t - 1, r = p / 7, c = p % 7;
      const float* ip = images + (size_t)gb * 784 + (r * 4) * 28 + c * 4;
      float px[16];
#pragma unroll
      for (int i = 0; i < 4; i++) {
        float4 v4 = *reinterpret_cast<const float4*>(ip + i * 28);
        px[4 * i + 0] = v4.x; px[4 * i + 1] = v4.y;
        px[4 * i + 2] = v4.z; px[4 * i + 3] = v4.w;
      }
#pragma unroll
      for (int d = 0; d < 8; d++) {
        const float* w = sw.linW + d * 16;
        float s = 0.f;
#pragma unroll
        for (int j = 0; j < 16; j++) s = fmaf(px[j], w[j], s);
        x[d] = s + sw.pos[t * 8 + d];
      }
    }
  };
  if (a0) embed(gb0, xA);
  if (a1) embed(gb1, xB);

  float* kv0 = skv[slot * 2];
  float* kv1 = skv[slot * 2 + 1];
  const float scale = 0.35355339059327373f;  // 8^-0.5

#pragma unroll 1
  for (int blk = 0; blk < NB; blk++) {
    float qA[8], qB[8];
    if (tok) {
      float hA[8], hB[8];
      layernorm(xA, sw.ln1g + blk * 8, sw.ln1b + blk * 8, hA);
      layernorm(xB, sw.ln1g + blk * 8, sw.ln1b + blk * 8, hB);
      const float* wq = sw.Wq + blk * 64;
      const float* wk = sw.Wk + blk * 64;
      const float* wv = sw.Wv + blk * 64;
      float* r0 = kv0 + t * 16;
      float* r1 = kv1 + t * 16;
#pragma unroll
      for (int e = 0; e < 8; e++) {
        float ka, kb, va, vb;
        dot8_2(wq + e * 8, hA, hB, qA[e], qB[e]);
        qA[e] *= scale; qB[e] *= scale;
        dot8_2(wk + e * 8, hA, hB, ka, kb);
        dot8_2(wv + e * 8, hA, hB, va, vb);
        r0[e] = ka; r0[8 + e] = va;
        r1[e] = kb; r1[8 + e] = vb;
      }
    }
    __syncthreads();

    float oA[8], oB[8];
    if (tok) {
      OS s00, s01, s10, s11;  // (imgA,h0) (imgA,h1) (imgB,h0) (imgB,h1)
      os_init(s00); os_init(s01); os_init(s10); os_init(s11);
      float4 qa0 = make_float4(qA[0], qA[1], qA[2], qA[3]);
      float4 qa1 = make_float4(qA[4], qA[5], qA[6], qA[7]);
      float4 qb0 = make_float4(qB[0], qB[1], qB[2], qB[3]);
      float4 qb1 = make_float4(qB[4], qB[5], qB[6], qB[7]);
#pragma unroll 2
      for (int u = 0; u < TT; u++) {
        const float4* p0 = reinterpret_cast<const float4*>(kv0 + u * 16);
        float4 k00 = p0[0], k01 = p0[1], v00 = p0[2], v01 = p0[3];
        os_upd(s00, qa0, k00, v00);
        os_upd(s01, qa1, k01, v01);
        const float4* p1 = reinterpret_cast<const float4*>(kv1 + u * 16);
        float4 k10 = p1[0], k11 = p1[1], v10 = p1[2], v11 = p1[3];
        os_upd(s10, qb0, k10, v10);
        os_upd(s11, qb1, k11, v11);
      }
      float i00 = 1.f / s00.l, i01 = 1.f / s01.l;
      float i10 = 1.f / s10.l, i11 = 1.f / s11.l;
      oA[0] = s00.a.x * i00; oA[1] = s00.a.y * i00;
      oA[2] = s00.a.z * i00; oA[3] = s00.a.w * i00;
      oA[4] = s01.a.x * i01; oA[5] = s01.a.y * i01;
      oA[6] = s01.a.z * i01; oA[7] = s01.a.w * i01;
      oB[0] = s10.a.x * i10; oB[1] = s10.a.y * i10;
      oB[2] = s10.a.z * i10; oB[3] = s10.a.w * i10;
      oB[4] = s11.a.x * i11; oB[5] = s11.a.y * i11;
      oB[6] = s11.a.z * i11; oB[7] = s11.a.w * i11;
    }
    __syncthreads();  // kv consumed; next block may overwrite

    if (tok) {
      // proj + residual
      const float* pw = sw.projW + blk * 64;
      const float* pb = sw.projb + blk * 8;
#pragma unroll
      for (int e = 0; e < 8; e++) {
        float ra, rb;
        dot8_2(pw + e * 8, oA, oB, ra, rb);
        xA[e] += ra + pb[e];
        xB[e] += rb + pb[e];
      }

      // LN2
      float hA[8], hB[8];
      layernorm(xA, sw.ln2g + blk * 8, sw.ln2b + blk * 8, hA);
      layernorm(xB, sw.ln2g + blk * 8, sw.ln2b + blk * 8, hB);

      // MLP 8 -> 32 (relu) -> 8, both images share weight loads
      const float* w1  = sw.W1 + blk * 256;
      const float* b1  = sw.b1 + blk * 32;
      const float* w2t = sw.W2t + blk * 256;
      const float* b2  = sw.b2 + blk * 8;
      float accA[8], accB[8];
#pragma unroll
      for (int d = 0; d < 8; d++) { accA[d] = 0.f; accB[d] = 0.f; }
#pragma unroll 4
      for (int f = 0; f < 32; f++) {
        float fA, fB;
        dot8_2(w1 + f * 8, hA, hB, fA, fB);
        fA = fmaxf(fA + b1[f], 0.f);
        fB = fmaxf(fB + b1[f], 0.f);
        float4 w2a = *reinterpret_cast<const float4*>(w2t + f * 8);
        float4 w2b = *reinterpret_cast<const float4*>(w2t + f * 8 + 4);
        accA[0] = fmaf(fA, w2a.x, accA[0]); accB[0] = fmaf(fB, w2a.x, accB[0]);
        accA[1] = fmaf(fA, w2a.y, accA[1]); accB[1] = fmaf(fB, w2a.y, accB[1]);
        accA[2] = fmaf(fA, w2a.z, accA[2]); accB[2] = fmaf(fB, w2a.z, accB[2]);
        accA[3] = fmaf(fA, w2a.w, accA[3]); accB[3] = fmaf(fB, w2a.w, accB[3]);
        accA[4] = fmaf(fA, w2b.x, accA[4]); accB[4] = fmaf(fB, w2b.x, accB[4]);
        accA[5] = fmaf(fA, w2b.y, accA[5]); accB[5] = fmaf(fB, w2b.y, accB[5]);
        accA[6] = fmaf(fA, w2b.z, accA[6]); accB[6] = fmaf(fB, w2b.z, accB[6]);
        accA[7] = fmaf(fA, w2b.w, accA[7]); accB[7] = fmaf(fB, w2b.w, accB[7]);
      }
#pragma unroll
      for (int d = 0; d < 8; d++) {
        xA[d] += accA[d] + b2[d];
        xB[d] += accB[d] + b2[d];
      }
    }
  }

  // classification head on token 0: softmax(x0 @ mlpW^T + mlpb)
  if (t == 0) {
    auto head = [&](const float x[8], int gb) {
      float z[10];
      float zm = -1e30f;
#pragma unroll
      for (int c = 0; c < 10; c++) {
        const float* w = sw.mlpW + c * 8;
        float s = sw.mlpb[c];
#pragma unroll
        for (int j = 0; j < 8; j++) s = fmaf(x[j], w[j], s);
        z[c] = s;
        zm = fmaxf(zm, s);
      }
      float ssum = 0.f;
#pragma unroll
      for (int c = 0; c < 10; c++) { z[c] = __expf(z[c] - zm); ssum += z[c]; }
      float inv = 1.f / ssum;
#pragma unroll
      for (int c = 0; c < 10; c++) out[gb * 10 + c] = z[c] * inv;
    };
    if (a0) head(xA, gb0);
    if (a1) head(xB, gb1);
  }
}

extern "C" void kernel_launch(void* const* d_in, const int* in_sizes, int n_in,
                              void* d_out, int out_size) {
  const float* images = (const float*)d_in[0];
  const float* cls    = (const float*)d_in[1];
  const float* linW   = (const float*)d_in[2];
  const float* ln1g   = (const float*)d_in[3];
  const float* ln1b   = (const float*)d_in[4];
  const float* Wq     = (const float*)d_in[5];
  const float* Wk     = (const float*)d_in[6];
  const float* Wv     = (const float*)d_in[7];
  const float* projW  = (const float*)d_in[8];
  const float* projb  = (const float*)d_in[9];
  const float* ln2g   = (const float*)d_in[10];
  const float* ln2b   = (const float*)d_in[11];
  const float* W1     = (const float*)d_in[12];
  const float* b1     = (const float*)d_in[13];
  const float* W2     = (const float*)d_in[14];
  const float* b2     = (const float*)d_in[15];
  const float* mlpW   = (const float*)d_in[16];
  const float* mlpb   = (const float*)d_in[17];

  int B = in_sizes[0] / 784;
  dim3 grid((B + IPC - 1) / IPC);
  vit_kernel<<<grid, NTH>>>(images, cls, linW, ln1g, ln1b, Wq, Wk, Wv, projW,
                            projb, ln2g, ln2b, W1, b1, W2, b2, mlpW, mlpb,
                            (float*)d_out, B);
}

// round 4
// speedup vs baseline: 1.1511x; 1.1511x over previous
#include <cuda_runtime.h>

// Tiny-ViT fused forward, round 3: packed f32x2 (FFMA2) over the 2-image
// register blocking + branch-free no-max softmax.
//  - activations are {imgA,imgB} pairs in 64-bit regs; all linear algebra via
//    fma.rn.f32x2 (2 FLOP/instr, ptxas never emits it from C++)
//  - weights staged in shared PRE-DUPLICATED {w,w}
//  - K/V stored image-interleaved, 64B rows -> 4x LDS.128 per u per array
//  - softmax without max subtraction (scores provably |s| < ~3 here):
//    fully independent loop iterations, no branch, no serial max chain
// CTA: 256 threads = 4 slots x 64 threads x 2 images = 8 images per CTA.

namespace {
constexpr int NB  = 4;
constexpr int TT  = 50;
constexpr int NTH = 256;
constexpr int IPC = 8;
}

typedef unsigned long long u64;

__device__ __forceinline__ u64 pk2(float a, float b) {
  u64 r;
  asm("mov.b64 %0, {%1, %2};" : "=l"(r)
      : "r"(__float_as_uint(a)), "r"(__float_as_uint(b)));
  return r;
}
__device__ __forceinline__ void upk2(u64 v, float& a, float& b) {
  unsigned int x, y;
  asm("mov.b64 {%0, %1}, %2;" : "=r"(x), "=r"(y) : "l"(v));
  a = __uint_as_float(x); b = __uint_as_float(y);
}
__device__ __forceinline__ u64 fma2(u64 a, u64 b, u64 c) {
  u64 d;
  asm("fma.rn.f32x2 %0, %1, %2, %3;" : "=l"(d) : "l"(a), "l"(b), "l"(c));
  return d;
}
__device__ __forceinline__ u64 add2(u64 a, u64 b) {
  u64 d;
  asm("add.rn.f32x2 %0, %1, %2;" : "=l"(d) : "l"(a), "l"(b));
  return d;
}
__device__ __forceinline__ u64 mul2(u64 a, u64 b) {
  u64 d;
  asm("mul.rn.f32x2 %0, %1, %2;" : "=l"(d) : "l"(a), "l"(b));
  return d;
}

namespace {
struct SW {  // all-u64 section first (16B-aligned offsets), floats after
  u64 Wq[NB * 64], Wk[NB * 64], Wv[NB * 64], projW[NB * 64];  // dup {w,w}
  u64 W1[NB * 256], W2t[NB * 256];                             // dup
  u64 ln1g[NB * 8], ln1b[NB * 8], ln2g[NB * 8], ln2b[NB * 8];  // dup
  u64 projb[NB * 8], b1[NB * 32], b2[NB * 8];                  // dup
  u64 linW[128];                                               // dup [8][16]
  float cls[8];
  float pos[TT * 8];
  float mlpW[80], mlpb[12];
};
constexpr int KV_U64   = 4 * 2 * TT * 8;      // 4 slots x (k+v) x 50 x 8 u64
constexpr int KV_BYTES = KV_U64 * 8;          // 25600
}

// packed dot8: one weight row (8 dup-pairs = 4x LDS.128) x packed activations
__device__ __forceinline__ u64 dot8p(const u64* __restrict__ w, const u64 h[8]) {
  ulonglong2 w0 = reinterpret_cast<const ulonglong2*>(w)[0];
  ulonglong2 w1 = reinterpret_cast<const ulonglong2*>(w)[1];
  ulonglong2 w2 = reinterpret_cast<const ulonglong2*>(w)[2];
  ulonglong2 w3 = reinterpret_cast<const ulonglong2*>(w)[3];
  u64 s0 = mul2(h[0], w0.x);
  u64 s1 = mul2(h[1], w0.y);
  s0 = fma2(h[2], w1.x, s0);
  s1 = fma2(h[3], w1.y, s1);
  s0 = fma2(h[4], w2.x, s0);
  s1 = fma2(h[5], w2.y, s1);
  s0 = fma2(h[6], w3.x, s0);
  s1 = fma2(h[7], w3.y, s1);
  return add2(s0, s1);
}

__device__ __forceinline__ void lnp(const u64 x[8], const u64* __restrict__ g,
                                    const u64* __restrict__ b, u64 h[8]) {
  u64 s = add2(add2(add2(x[0], x[1]), add2(x[2], x[3])),
               add2(add2(x[4], x[5]), add2(x[6], x[7])));
  float sA, sB;
  upk2(s, sA, sB);
  u64 mu = pk2(sA * 0.125f, sB * 0.125f);
  const u64 N1 = pk2(-1.f, -1.f);
  u64 c[8];
#pragma unroll
  for (int d = 0; d < 8; d++) c[d] = fma2(mu, N1, x[d]);
  u64 v0 = mul2(c[0], c[0]);
  u64 v1 = mul2(c[1], c[1]);
  v0 = fma2(c[2], c[2], v0);
  v1 = fma2(c[3], c[3], v1);
  v0 = fma2(c[4], c[4], v0);
  v1 = fma2(c[5], c[5], v1);
  v0 = fma2(c[6], c[6], v0);
  v1 = fma2(c[7], c[7], v1);
  float vA, vB;
  upk2(add2(v0, v1), vA, vB);
  u64 rs = pk2(rsqrtf(fmaf(vA, 0.125f, 1e-5f)),
               rsqrtf(fmaf(vB, 0.125f, 1e-5f)));
#pragma unroll
  for (int d = 0; d < 8; d++) h[d] = fma2(mul2(c[d], rs), g[d], b[d]);
}

__global__ void __launch_bounds__(NTH) vit_kernel(
    const float* __restrict__ images, const float* __restrict__ cls_g,
    const float* __restrict__ linW_g, const float* __restrict__ ln1g_g,
    const float* __restrict__ ln1b_g, const float* __restrict__ Wq_g,
    const float* __restrict__ Wk_g, const float* __restrict__ Wv_g,
    const float* __restrict__ projW_g, const float* __restrict__ projb_g,
    const float* __restrict__ ln2g_g, const float* __restrict__ ln2b_g,
    const float* __restrict__ W1_g, const float* __restrict__ b1_g,
    const float* __restrict__ W2_g, const float* __restrict__ b2_g,
    const float* __restrict__ mlpW_g, const float* __restrict__ mlpb_g,
    float* __restrict__ out, int B) {
  extern __shared__ __align__(16) char dsm[];
  u64* skv = reinterpret_cast<u64*>(dsm);            // [4][2][50][8]
  SW* sw = reinterpret_cast<SW*>(dsm + KV_BYTES);

  const int tid = threadIdx.x;

  // ---- stage weights (duplicated pairs) ----
  {
    auto dup = [&](u64* d, const float* s, int n) {
      for (int i = tid; i < n; i += NTH) { float w = s[i]; d[i] = pk2(w, w); }
    };
    dup(sw->Wq, Wq_g, NB * 64);
    dup(sw->Wk, Wk_g, NB * 64);
    dup(sw->Wv, Wv_g, NB * 64);
    dup(sw->projW, projW_g, NB * 64);
    dup(sw->W1, W1_g, NB * 256);
    dup(sw->ln1g, ln1g_g, NB * 8);  dup(sw->ln1b, ln1b_g, NB * 8);
    dup(sw->ln2g, ln2g_g, NB * 8);  dup(sw->ln2b, ln2b_g, NB * 8);
    dup(sw->projb, projb_g, NB * 8);
    dup(sw->b1, b1_g, NB * 32);
    dup(sw->b2, b2_g, NB * 8);
    dup(sw->linW, linW_g, 128);
    // W2 [blk][8][32] -> transposed dup [blk][32][8]
    for (int i = tid; i < NB * 256; i += NTH) {
      int blk = i >> 8, rem = i & 255, f = rem >> 3, d = rem & 7;
      float w = W2_g[blk * 256 + d * 32 + f];
      sw->W2t[blk * 256 + rem] = pk2(w, w);
    }
    for (int i = tid; i < 8; i += NTH) sw->cls[i] = cls_g[i];
    for (int i = tid; i < 80; i += NTH) sw->mlpW[i] = mlpW_g[i];
    for (int i = tid; i < 10; i += NTH) sw->mlpb[i] = mlpb_g[i];
    if (tid < TT) {  // sinusoidal table: freqs {1, .1, .01, .001}
      float tf = (float)tid;
      float* p = sw->pos + tid * 8;
      p[0] = sinf(tf);          p[1] = cosf(tf);
      p[2] = sinf(tf * 0.1f);   p[3] = cosf(tf * 0.1f);
      p[4] = sinf(tf * 0.01f);  p[5] = cosf(tf * 0.01f);
      p[6] = sinf(tf * 0.001f); p[7] = cosf(tf * 0.001f);
    }
  }
  __syncthreads();

  const int slot = tid >> 6;
  const int t    = tid & 63;
  const int gb0  = blockIdx.x * IPC + slot * 2;
  const int gb1  = gb0 + 1;
  const bool tok = (t < TT);
  const bool a0  = tok && (gb0 < B);
  const bool a1  = tok && (gb1 < B);

  u64* kbase = skv + slot * (2 * TT * 8);
  u64* vbase = kbase + TT * 8;

  u64 X[8];
#pragma unroll
  for (int d = 0; d < 8; d++) X[d] = 0;

  // ---- patch embed + positional ----
  if (tok) {
    if (t == 0) {
#pragma unroll
      for (int d = 0; d < 8; d++) {
        float v = sw->cls[d] + sw->pos[d];
        X[d] = pk2(v, v);
      }
    } else {
      int p = t - 1, r = p / 7, c = p % 7;
      float pxA[16], pxB[16];
#pragma unroll
      for (int j = 0; j < 16; j++) { pxA[j] = 0.f; pxB[j] = 0.f; }
      if (a0) {
        const float* ip = images + (size_t)gb0 * 784 + (r * 4) * 28 + c * 4;
#pragma unroll
        for (int i = 0; i < 4; i++) {
          float4 v4 = *reinterpret_cast<const float4*>(ip + i * 28);
          pxA[4 * i] = v4.x; pxA[4 * i + 1] = v4.y;
          pxA[4 * i + 2] = v4.z; pxA[4 * i + 3] = v4.w;
        }
      }
      if (a1) {
        const float* ip = images + (size_t)gb1 * 784 + (r * 4) * 28 + c * 4;
#pragma unroll
        for (int i = 0; i < 4; i++) {
          float4 v4 = *reinterpret_cast<const float4*>(ip + i * 28);
          pxB[4 * i] = v4.x; pxB[4 * i + 1] = v4.y;
          pxB[4 * i + 2] = v4.z; pxB[4 * i + 3] = v4.w;
        }
      }
      u64 pp[16];
#pragma unroll
      for (int j = 0; j < 16; j++) pp[j] = pk2(pxA[j], pxB[j]);
#pragma unroll
      for (int d = 0; d < 8; d++) {
        const u64* lw = sw->linW + d * 16;
        u64 s0 = mul2(pp[0], lw[0]);
        u64 s1 = mul2(pp[1], lw[1]);
#pragma unroll
        for (int j = 2; j < 16; j += 2) {
          s0 = fma2(pp[j], lw[j], s0);
          s1 = fma2(pp[j + 1], lw[j + 1], s1);
        }
        float ps = sw->pos[t * 8 + d];
        X[d] = add2(add2(s0, s1), pk2(ps, ps));
      }
    }
  }

#pragma unroll 1
  for (int blk = 0; blk < NB; blk++) {
    u64 Q[8];
    if (tok) {
      u64 H[8];
      lnp(X, sw->ln1g + blk * 8, sw->ln1b + blk * 8, H);
      const u64* wq = sw->Wq + blk * 64;
      const u64* wk = sw->Wk + blk * 64;
      const u64* wv = sw->Wv + blk * 64;
      u64* kr = kbase + t * 8;
      u64* vr = vbase + t * 8;
      const u64 SC2 = pk2(0.35355339059327373f, 0.35355339059327373f);
#pragma unroll
      for (int e = 0; e < 8; e++) {
        Q[e] = mul2(dot8p(wq + e * 8, H), SC2);
        kr[e] = dot8p(wk + e * 8, H);
        vr[e] = dot8p(wv + e * 8, H);
      }
    }
    __syncthreads();

    u64 O[8];
    if (tok) {
      // branch-free softmax without max subtraction (scores tiny by design)
      u64 l0 = 0, l1 = 0;
      u64 a00 = 0, a01 = 0, a02 = 0, a03 = 0;
      u64 a10 = 0, a11 = 0, a12 = 0, a13 = 0;
#pragma unroll 2
      for (int u = 0; u < TT; u++) {
        const ulonglong2* kp = reinterpret_cast<const ulonglong2*>(kbase + u * 8);
        ulonglong2 k0 = kp[0], k1 = kp[1], k2 = kp[2], k3 = kp[3];
        const ulonglong2* vp = reinterpret_cast<const ulonglong2*>(vbase + u * 8);
        ulonglong2 v0 = vp[0], v1 = vp[1], v2 = vp[2], v3 = vp[3];
        u64 s0 = fma2(Q[0], k0.x,
                 fma2(Q[1], k0.y, fma2(Q[2], k1.x, mul2(Q[3], k1.y))));
        u64 s1 = fma2(Q[4], k2.x,
                 fma2(Q[5], k2.y, fma2(Q[6], k3.x, mul2(Q[7], k3.y))));
        float sa, sb, sc, sd;
        upk2(s0, sa, sb);
        upk2(s1, sc, sd);
        u64 p0 = pk2(__expf(sa), __expf(sb));
        u64 p1 = pk2(__expf(sc), __expf(sd));
        l0 = add2(l0, p0);
        l1 = add2(l1, p1);
        a00 = fma2(p0, v0.x, a00); a01 = fma2(p0, v0.y, a01);
        a02 = fma2(p0, v1.x, a02); a03 = fma2(p0, v1.y, a03);
        a10 = fma2(p1, v2.x, a10); a11 = fma2(p1, v2.y, a11);
        a12 = fma2(p1, v3.x, a12); a13 = fma2(p1, v3.y, a13);
      }
      float lA, lB;
      upk2(l0, lA, lB);
      u64 i0 = pk2(1.f / lA, 1.f / lB);
      upk2(l1, lA, lB);
      u64 i1 = pk2(1.f / lA, 1.f / lB);
      O[0] = mul2(a00, i0); O[1] = mul2(a01, i0);
      O[2] = mul2(a02, i0); O[3] = mul2(a03, i0);
      O[4] = mul2(a10, i1); O[5] = mul2(a11, i1);
      O[6] = mul2(a12, i1); O[7] = mul2(a13, i1);
    }
    __syncthreads();  // kv consumed

    if (tok) {
      const u64* pw = sw->projW + blk * 64;
      const u64* pb = sw->projb + blk * 8;
#pragma unroll
      for (int e = 0; e < 8; e++)
        X[e] = add2(X[e], add2(dot8p(pw + e * 8, O), pb[e]));

      u64 H2[8];
      lnp(X, sw->ln2g + blk * 8, sw->ln2b + blk * 8, H2);

      const u64* w1 = sw->W1 + blk * 256;
      const u64* b1 = sw->b1 + blk * 32;
      const u64* w2 = sw->W2t + blk * 256;
      u64 acc[8];
#pragma unroll
      for (int d = 0; d < 8; d++) acc[d] = 0;
#pragma unroll 4
      for (int f = 0; f < 32; f++) {
        u64 fv = add2(dot8p(w1 + f * 8, H2), b1[f]);
        float fa, fb;
        upk2(fv, fa, fb);
        fv = pk2(fmaxf(fa, 0.f), fmaxf(fb, 0.f));
        const ulonglong2* wr = reinterpret_cast<const ulonglong2*>(w2 + f * 8);
        ulonglong2 m0 = wr[0], m1 = wr[1], m2 = wr[2], m3 = wr[3];
        acc[0] = fma2(fv, m0.x, acc[0]); acc[1] = fma2(fv, m0.y, acc[1]);
        acc[2] = fma2(fv, m1.x, acc[2]); acc[3] = fma2(fv, m1.y, acc[3]);
        acc[4] = fma2(fv, m2.x, acc[4]); acc[5] = fma2(fv, m2.y, acc[5]);
        acc[6] = fma2(fv, m3.x, acc[6]); acc[7] = fma2(fv, m3.y, acc[7]);
      }
      const u64* b2 = sw->b2 + blk * 8;
#pragma unroll
      for (int d = 0; d < 8; d++) X[d] = add2(X[d], add2(acc[d], b2[d]));
    }
  }

  // classification head on token 0: softmax(x0 @ mlpW^T + mlpb)
  if (t == 0) {
    float xA[8], xB[8];
#pragma unroll
    for (int d = 0; d < 8; d++) upk2(X[d], xA[d], xB[d]);
    auto head = [&](const float x[8], int gb) {
      float z[10];
      float zm = -1e30f;
#pragma unroll
      for (int c = 0; c < 10; c++) {
        const float* w = sw->mlpW + c * 8;
        float s = sw->mlpb[c];
#pragma unroll
        for (int j = 0; j < 8; j++) s = fmaf(x[j], w[j], s);
        z[c] = s;
        zm = fmaxf(zm, s);
      }
      float ssum = 0.f;
#pragma unroll
      for (int c = 0; c < 10; c++) { z[c] = __expf(z[c] - zm); ssum += z[c]; }
      float inv = 1.f / ssum;
#pragma unroll
      for (int c = 0; c < 10; c++) out[gb * 10 + c] = z[c] * inv;
    };
    if (a0) head(xA, gb0);
    if (a1) head(xB, gb1);
  }
}

extern "C" void kernel_launch(void* const* d_in, const int* in_sizes, int n_in,
                              void* d_out, int out_size) {
  const float* images = (const float*)d_in[0];
  const float* cls    = (const float*)d_in[1];
  const float* linW   = (const float*)d_in[2];
  const float* ln1g   = (const float*)d_in[3];
  const float* ln1b   = (const float*)d_in[4];
  const float* Wq     = (const float*)d_in[5];
  const float* Wk     = (const float*)d_in[6];
  const float* Wv     = (const float*)d_in[7];
  const float* projW  = (const float*)d_in[8];
  const float* projb  = (const float*)d_in[9];
  const float* ln2g   = (const float*)d_in[10];
  const float* ln2b   = (const float*)d_in[11];
  const float* W1     = (const float*)d_in[12];
  const float* b1     = (const float*)d_in[13];
  const float* W2     = (const float*)d_in[14];
  const float* b2     = (const float*)d_in[15];
  const float* mlpW   = (const float*)d_in[16];
  const float* mlpb   = (const float*)d_in[17];

  int B = in_sizes[0] / 784;
  int smem = KV_BYTES + (int)sizeof(SW);
  cudaFuncSetAttribute(vit_kernel, cudaFuncAttributeMaxDynamicSharedMemorySize,
                       smem);
  dim3 grid((B + IPC - 1) / IPC);
  vit_kernel<<<grid, NTH, smem>>>(images, cls, linW, ln1g, ln1b, Wq, Wk, Wv,
                                  projW, projb, ln2g, ln2b, W1, b1, W2, b2,
                                  mlpW, mlpb, (float*)d_out, B);
}

// round 5
// speedup vs baseline: 1.4180x; 1.2319x over previous
#include <cuda_runtime.h>

// Tiny-ViT fused forward, round 4: R3 (packed f32x2 + no-max softmax)
// + occupancy fix:
//  - __launch_bounds__(256, 2): reg cap 128 -> 2 CTAs/SM (16 warps, was 8)
//  - attention loop unroll 1 (halves live k/v regs; 10 indep chains remain)
//  - ex2.approx with log2e folded into Q scale (1 MUFU per exp, no mul)
//  - K/V rows written via STS.128 vectors
// CTA: 256 threads = 4 slots x 64 threads x 2 images = 8 images per CTA.

namespace {
constexpr int NB  = 4;
constexpr int TT  = 50;
constexpr int NTH = 256;
constexpr int IPC = 8;
}

typedef unsigned long long u64;

__device__ __forceinline__ u64 pk2(float a, float b) {
  u64 r;
  asm("mov.b64 %0, {%1, %2};" : "=l"(r)
      : "r"(__float_as_uint(a)), "r"(__float_as_uint(b)));
  return r;
}
__device__ __forceinline__ void upk2(u64 v, float& a, float& b) {
  unsigned int x, y;
  asm("mov.b64 {%0, %1}, %2;" : "=r"(x), "=r"(y) : "l"(v));
  a = __uint_as_float(x); b = __uint_as_float(y);
}
__device__ __forceinline__ u64 fma2(u64 a, u64 b, u64 c) {
  u64 d;
  asm("fma.rn.f32x2 %0, %1, %2, %3;" : "=l"(d) : "l"(a), "l"(b), "l"(c));
  return d;
}
__device__ __forceinline__ u64 add2(u64 a, u64 b) {
  u64 d;
  asm("add.rn.f32x2 %0, %1, %2;" : "=l"(d) : "l"(a), "l"(b));
  return d;
}
__device__ __forceinline__ u64 mul2(u64 a, u64 b) {
  u64 d;
  asm("mul.rn.f32x2 %0, %1, %2;" : "=l"(d) : "l"(a), "l"(b));
  return d;
}
__device__ __forceinline__ float ex2f(float x) {
  float r;
  asm("ex2.approx.ftz.f32 %0, %1;" : "=f"(r) : "f"(x));
  return r;
}

namespace {
struct SW {  // all-u64 section first, floats after
  u64 Wq[NB * 64], Wk[NB * 64], Wv[NB * 64], projW[NB * 64];  // dup {w,w}
  u64 W1[NB * 256], W2t[NB * 256];                             // dup
  u64 ln1g[NB * 8], ln1b[NB * 8], ln2g[NB * 8], ln2b[NB * 8];  // dup
  u64 projb[NB * 8], b1[NB * 32], b2[NB * 8];                  // dup
  u64 linW[128];                                               // dup [8][16]
  float cls[8];
  float pos[TT * 8];
  float mlpW[80], mlpb[12];
};
constexpr int KV_U64   = 4 * 2 * TT * 8;      // 4 slots x (k+v) x 50 x 8 u64
constexpr int KV_BYTES = KV_U64 * 8;          // 25600
}

// packed dot8: one weight row (8 dup-pairs = 4x LDS.128 broadcast) x acts
__device__ __forceinline__ u64 dot8p(const u64* __restrict__ w, const u64 h[8]) {
  ulonglong2 w0 = reinterpret_cast<const ulonglong2*>(w)[0];
  ulonglong2 w1 = reinterpret_cast<const ulonglong2*>(w)[1];
  ulonglong2 w2 = reinterpret_cast<const ulonglong2*>(w)[2];
  ulonglong2 w3 = reinterpret_cast<const ulonglong2*>(w)[3];
  u64 s0 = mul2(h[0], w0.x);
  u64 s1 = mul2(h[1], w0.y);
  s0 = fma2(h[2], w1.x, s0);
  s1 = fma2(h[3], w1.y, s1);
  s0 = fma2(h[4], w2.x, s0);
  s1 = fma2(h[5], w2.y, s1);
  s0 = fma2(h[6], w3.x, s0);
  s1 = fma2(h[7], w3.y, s1);
  return add2(s0, s1);
}

__device__ __forceinline__ void lnp(const u64 x[8], const u64* __restrict__ g,
                                    const u64* __restrict__ b, u64 h[8]) {
  u64 s = add2(add2(add2(x[0], x[1]), add2(x[2], x[3])),
               add2(add2(x[4], x[5]), add2(x[6], x[7])));
  float sA, sB;
  upk2(s, sA, sB);
  u64 mu = pk2(sA * 0.125f, sB * 0.125f);
  const u64 N1 = pk2(-1.f, -1.f);
  u64 c[8];
#pragma unroll
  for (int d = 0; d < 8; d++) c[d] = fma2(mu, N1, x[d]);
  u64 v0 = mul2(c[0], c[0]);
  u64 v1 = mul2(c[1], c[1]);
  v0 = fma2(c[2], c[2], v0);
  v1 = fma2(c[3], c[3], v1);
  v0 = fma2(c[4], c[4], v0);
  v1 = fma2(c[5], c[5], v1);
  v0 = fma2(c[6], c[6], v0);
  v1 = fma2(c[7], c[7], v1);
  float vA, vB;
  upk2(add2(v0, v1), vA, vB);
  u64 rs = pk2(rsqrtf(fmaf(vA, 0.125f, 1e-5f)),
               rsqrtf(fmaf(vB, 0.125f, 1e-5f)));
#pragma unroll
  for (int d = 0; d < 8; d++) h[d] = fma2(mul2(c[d], rs), g[d], b[d]);
}

__global__ void __launch_bounds__(NTH, 2) vit_kernel(
    const float* __restrict__ images, const float* __restrict__ cls_g,
    const float* __restrict__ linW_g, const float* __restrict__ ln1g_g,
    const float* __restrict__ ln1b_g, const float* __restrict__ Wq_g,
    const float* __restrict__ Wk_g, const float* __restrict__ Wv_g,
    const float* __restrict__ projW_g, const float* __restrict__ projb_g,
    const float* __restrict__ ln2g_g, const float* __restrict__ ln2b_g,
    const float* __restrict__ W1_g, const float* __restrict__ b1_g,
    const float* __restrict__ W2_g, const float* __restrict__ b2_g,
    const float* __restrict__ mlpW_g, const float* __restrict__ mlpb_g,
    float* __restrict__ out, int B) {
  extern __shared__ __align__(16) char dsm[];
  u64* skv = reinterpret_cast<u64*>(dsm);            // [4][2][50][8]
  SW* sw = reinterpret_cast<SW*>(dsm + KV_BYTES);

  const int tid = threadIdx.x;

  // ---- stage weights (duplicated pairs) ----
  {
    auto dup = [&](u64* d, const float* s, int n) {
      for (int i = tid; i < n; i += NTH) { float w = s[i]; d[i] = pk2(w, w); }
    };
    dup(sw->Wq, Wq_g, NB * 64);
    dup(sw->Wk, Wk_g, NB * 64);
    dup(sw->Wv, Wv_g, NB * 64);
    dup(sw->projW, projW_g, NB * 64);
    dup(sw->W1, W1_g, NB * 256);
    dup(sw->ln1g, ln1g_g, NB * 8);  dup(sw->ln1b, ln1b_g, NB * 8);
    dup(sw->ln2g, ln2g_g, NB * 8);  dup(sw->ln2b, ln2b_g, NB * 8);
    dup(sw->projb, projb_g, NB * 8);
    dup(sw->b1, b1_g, NB * 32);
    dup(sw->b2, b2_g, NB * 8);
    dup(sw->linW, linW_g, 128);
    // W2 [blk][8][32] -> transposed dup [blk][32][8]
    for (int i = tid; i < NB * 256; i += NTH) {
      int blk = i >> 8, rem = i & 255, f = rem >> 3, d = rem & 7;
      float w = W2_g[blk * 256 + d * 32 + f];
      sw->W2t[blk * 256 + rem] = pk2(w, w);
    }
    for (int i = tid; i < 8; i += NTH) sw->cls[i] = cls_g[i];
    for (int i = tid; i < 80; i += NTH) sw->mlpW[i] = mlpW_g[i];
    for (int i = tid; i < 10; i += NTH) sw->mlpb[i] = mlpb_g[i];
    if (tid < TT) {  // sinusoidal table: freqs {1, .1, .01, .001}
      float tf = (float)tid;
      float* p = sw->pos + tid * 8;
      p[0] = sinf(tf);          p[1] = cosf(tf);
      p[2] = sinf(tf * 0.1f);   p[3] = cosf(tf * 0.1f);
      p[4] = sinf(tf * 0.01f);  p[5] = cosf(tf * 0.01f);
      p[6] = sinf(tf * 0.001f); p[7] = cosf(tf * 0.001f);
    }
  }
  __syncthreads();

  const int slot = tid >> 6;
  const int t    = tid & 63;
  const int gb0  = blockIdx.x * IPC + slot * 2;
  const int gb1  = gb0 + 1;
  const bool tok = (t < TT);
  const bool a0  = tok && (gb0 < B);
  const bool a1  = tok && (gb1 < B);

  u64* kbase = skv + slot * (2 * TT * 8);
  u64* vbase = kbase + TT * 8;

  u64 X[8];
#pragma unroll
  for (int d = 0; d < 8; d++) X[d] = 0;

  // ---- patch embed + positional ----
  if (tok) {
    if (t == 0) {
#pragma unroll
      for (int d = 0; d < 8; d++) {
        float v = sw->cls[d] + sw->pos[d];
        X[d] = pk2(v, v);
      }
    } else {
      int p = t - 1, r = p / 7, c = p % 7;
      float pxA[16], pxB[16];
#pragma unroll
      for (int j = 0; j < 16; j++) { pxA[j] = 0.f; pxB[j] = 0.f; }
      if (a0) {
        const float* ip = images + (size_t)gb0 * 784 + (r * 4) * 28 + c * 4;
#pragma unroll
        for (int i = 0; i < 4; i++) {
          float4 v4 = *reinterpret_cast<const float4*>(ip + i * 28);
          pxA[4 * i] = v4.x; pxA[4 * i + 1] = v4.y;
          pxA[4 * i + 2] = v4.z; pxA[4 * i + 3] = v4.w;
        }
      }
      if (a1) {
        const float* ip = images + (size_t)gb1 * 784 + (r * 4) * 28 + c * 4;
#pragma unroll
        for (int i = 0; i < 4; i++) {
          float4 v4 = *reinterpret_cast<const float4*>(ip + i * 28);
          pxB[4 * i] = v4.x; pxB[4 * i + 1] = v4.y;
          pxB[4 * i + 2] = v4.z; pxB[4 * i + 3] = v4.w;
        }
      }
      u64 pp[16];
#pragma unroll
      for (int j = 0; j < 16; j++) pp[j] = pk2(pxA[j], pxB[j]);
#pragma unroll
      for (int d = 0; d < 8; d++) {
        const u64* lw = sw->linW + d * 16;
        u64 s0 = mul2(pp[0], lw[0]);
        u64 s1 = mul2(pp[1], lw[1]);
#pragma unroll
        for (int j = 2; j < 16; j += 2) {
          s0 = fma2(pp[j], lw[j], s0);
          s1 = fma2(pp[j + 1], lw[j + 1], s1);
        }
        float ps = sw->pos[t * 8 + d];
        X[d] = add2(add2(s0, s1), pk2(ps, ps));
      }
    }
  }

  // scale * log2(e): softmax computed in base-2 (exp2(s*scale*log2e)=exp(s*scale))
  const float SCL2E = 0.35355339059327373f * 1.4426950408889634f;

#pragma unroll 1
  for (int blk = 0; blk < NB; blk++) {
    u64 Q[8];
    if (tok) {
      u64 H[8];
      lnp(X, sw->ln1g + blk * 8, sw->ln1b + blk * 8, H);
      const u64* wq = sw->Wq + blk * 64;
      const u64* wk = sw->Wk + blk * 64;
      const u64* wv = sw->Wv + blk * 64;
      const u64 SC2 = pk2(SCL2E, SCL2E);
      u64 kv[8];
#pragma unroll
      for (int e = 0; e < 8; e++) {
        Q[e] = mul2(dot8p(wq + e * 8, H), SC2);
        kv[e] = dot8p(wk + e * 8, H);
      }
      ulonglong2* kr = reinterpret_cast<ulonglong2*>(kbase + t * 8);
      kr[0] = make_ulonglong2(kv[0], kv[1]);
      kr[1] = make_ulonglong2(kv[2], kv[3]);
      kr[2] = make_ulonglong2(kv[4], kv[5]);
      kr[3] = make_ulonglong2(kv[6], kv[7]);
#pragma unroll
      for (int e = 0; e < 8; e++) kv[e] = dot8p(wv + e * 8, H);
      ulonglong2* vr = reinterpret_cast<ulonglong2*>(vbase + t * 8);
      vr[0] = make_ulonglong2(kv[0], kv[1]);
      vr[1] = make_ulonglong2(kv[2], kv[3]);
      vr[2] = make_ulonglong2(kv[4], kv[5]);
      vr[3] = make_ulonglong2(kv[6], kv[7]);
    }
    __syncthreads();

    u64 O[8];
    if (tok) {
      // branch-free softmax in base 2, no max subtraction (scores tiny)
      u64 l0 = 0, l1 = 0;
      u64 a00 = 0, a01 = 0, a02 = 0, a03 = 0;
      u64 a10 = 0, a11 = 0, a12 = 0, a13 = 0;
#pragma unroll 1
      for (int u = 0; u < TT; u++) {
        const ulonglong2* kp = reinterpret_cast<const ulonglong2*>(kbase + u * 8);
        ulonglong2 k0 = kp[0], k1 = kp[1], k2 = kp[2], k3 = kp[3];
        u64 s0 = fma2(Q[0], k0.x,
                 fma2(Q[1], k0.y, fma2(Q[2], k1.x, mul2(Q[3], k1.y))));
        u64 s1 = fma2(Q[4], k2.x,
                 fma2(Q[5], k2.y, fma2(Q[6], k3.x, mul2(Q[7], k3.y))));
        const ulonglong2* vp = reinterpret_cast<const ulonglong2*>(vbase + u * 8);
        ulonglong2 v0 = vp[0], v1 = vp[1], v2 = vp[2], v3 = vp[3];
        float sa, sb, sc, sd;
        upk2(s0, sa, sb);
        upk2(s1, sc, sd);
        u64 p0 = pk2(ex2f(sa), ex2f(sb));
        u64 p1 = pk2(ex2f(sc), ex2f(sd));
        l0 = add2(l0, p0);
        l1 = add2(l1, p1);
        a00 = fma2(p0, v0.x, a00); a01 = fma2(p0, v0.y, a01);
        a02 = fma2(p0, v1.x, a02); a03 = fma2(p0, v1.y, a03);
        a10 = fma2(p1, v2.x, a10); a11 = fma2(p1, v2.y, a11);
        a12 = fma2(p1, v3.x, a12); a13 = fma2(p1, v3.y, a13);
      }
      float lA, lB;
      upk2(l0, lA, lB);
      u64 i0 = pk2(1.f / lA, 1.f / lB);
      upk2(l1, lA, lB);
      u64 i1 = pk2(1.f / lA, 1.f / lB);
      O[0] = mul2(a00, i0); O[1] = mul2(a01, i0);
      O[2] = mul2(a02, i0); O[3] = mul2(a03, i0);
      O[4] = mul2(a10, i1); O[5] = mul2(a11, i1);
      O[6] = mul2(a12, i1); O[7] = mul2(a13, i1);
    }
    __syncthreads();  // kv consumed

    if (tok) {
      const u64* pw = sw->projW + blk * 64;
      const u64* pb = sw->projb + blk * 8;
#pragma unroll
      for (int e = 0; e < 8; e++)
        X[e] = add2(X[e], add2(dot8p(pw + e * 8, O), pb[e]));

      u64 H2[8];
      lnp(X, sw->ln2g + blk * 8, sw->ln2b + blk * 8, H2);

      const u64* w1 = sw->W1 + blk * 256;
      const u64* b1 = sw->b1 + blk * 32;
      const u64* w2 = sw->W2t + blk * 256;
      u64 acc[8];
#pragma unroll
      for (int d = 0; d < 8; d++) acc[d] = 0;
#pragma unroll 2
      for (int f = 0; f < 32; f++) {
        u64 fv = add2(dot8p(w1 + f * 8, H2), b1[f]);
        float fa, fb;
        upk2(fv, fa, fb);
        fv = pk2(fmaxf(fa, 0.f), fmaxf(fb, 0.f));
        const ulonglong2* wr = reinterpret_cast<const ulonglong2*>(w2 + f * 8);
        ulonglong2 m0 = wr[0], m1 = wr[1], m2 = wr[2], m3 = wr[3];
        acc[0] = fma2(fv, m0.x, acc[0]); acc[1] = fma2(fv, m0.y, acc[1]);
        acc[2] = fma2(fv, m1.x, acc[2]); acc[3] = fma2(fv, m1.y, acc[3]);
        acc[4] = fma2(fv, m2.x, acc[4]); acc[5] = fma2(fv, m2.y, acc[5]);
        acc[6] = fma2(fv, m3.x, acc[6]); acc[7] = fma2(fv, m3.y, acc[7]);
      }
      const u64* b2 = sw->b2 + blk * 8;
#pragma unroll
      for (int d = 0; d < 8; d++) X[d] = add2(X[d], add2(acc[d], b2[d]));
    }
  }

  // classification head on token 0: softmax(x0 @ mlpW^T + mlpb)
  if (t == 0) {
    float xA[8], xB[8];
#pragma unroll
    for (int d = 0; d < 8; d++) upk2(X[d], xA[d], xB[d]);
    auto head = [&](const float x[8], int gb) {
      float z[10];
      float zm = -1e30f;
#pragma unroll
      for (int c = 0; c < 10; c++) {
        const float* w = sw->mlpW + c * 8;
        float s = sw->mlpb[c];
#pragma unroll
        for (int j = 0; j < 8; j++) s = fmaf(x[j], w[j], s);
        z[c] = s;
        zm = fmaxf(zm, s);
      }
      float ssum = 0.f;
#pragma unroll
      for (int c = 0; c < 10; c++) { z[c] = __expf(z[c] - zm); ssum += z[c]; }
      float inv = 1.f / ssum;
#pragma unroll
      for (int c = 0; c < 10; c++) out[gb * 10 + c] = z[c] * inv;
    };
    if (a0) head(xA, gb0);
    if (a1) head(xB, gb1);
  }
}

extern "C" void kernel_launch(void* const* d_in, const int* in_sizes, int n_in,
                              void* d_out, int out_size) {
  const float* images = (const float*)d_in[0];
  const float* cls    = (const float*)d_in[1];
  const float* linW   = (const float*)d_in[2];
  const float* ln1g   = (const float*)d_in[3];
  const float* ln1b   = (const float*)d_in[4];
  const float* Wq     = (const float*)d_in[5];
  const float* Wk     = (const float*)d_in[6];
  const float* Wv     = (const float*)d_in[7];
  const float* projW  = (const float*)d_in[8];
  const float* projb  = (const float*)d_in[9];
  const float* ln2g   = (const float*)d_in[10];
  const float* ln2b   = (const float*)d_in[11];
  const float* W1     = (const float*)d_in[12];
  const float* b1     = (const float*)d_in[13];
  const float* W2     = (const float*)d_in[14];
  const float* b2     = (const float*)d_in[15];
  const float* mlpW   = (const float*)d_in[16];
  const float* mlpb   = (const float*)d_in[17];

  int B = in_sizes[0] / 784;
  int smem = KV_BYTES + (int)sizeof(SW);
  cudaFuncSetAttribute(vit_kernel, cudaFuncAttributeMaxDynamicSharedMemorySize,
                       smem);
  dim3 grid((B + IPC - 1) / IPC);
  vit_kernel<<<grid, NTH, smem>>>(images, cls, linW, ln1g, ln1b, Wq, Wk, Wv,
                                  projW, projb, ln2g, ln2b, W1, b1, W2, b2,
                                  mlpW, mlpb, (float*)d_out, B);
}

// round 7
// speedup vs baseline: 1.5052x; 1.0615x over previous
#include <cuda_runtime.h>

// Tiny-ViT fused forward, round 5 (resubmit — infra container failure, kernel
// never ran): 2 tokens x 2 images per thread.
//  - warp = slot: 25 active lanes own tokens {lane, lane+25} of 2 images
//    -> every K/V and weight broadcast LDS feeds 4 streams (was 2)
//  - weights stored de-duplicated fp32; packed {w,w} via 1-instr mov on ALU
//  - X stashed to per-thread smem during QKV/attention and MLP (reg relief)
//  - f32x2 math, base-2 no-max softmax (R4) retained
// CTA: 256 threads = 8 warps = 8 slots = 16 images. grid = B/16.

namespace {
constexpr int NB  = 4;
constexpr int TT  = 50;
constexpr int NTH = 256;
constexpr int WPC = 8;     // warps (slots) per CTA
constexpr int IPC = 16;    // images per CTA
constexpr int ROW  = 18;   // u64 per kv token row (144B: k[0..7], pad, v[10..17])
constexpr int VOFF = 10;
constexpr int KV_U64 = WPC * TT * ROW;        // 7200
constexpr int ST_STR = 18;                    // stash stride (u64), 16B aligned
constexpr int ST_U64 = WPC * 25 * ST_STR;     // 3600

struct SW {  // de-duplicated fp32 weights
  float Wq[NB * 64], Wk[NB * 64], Wv[NB * 64], projW[NB * 64];
  float W1[NB * 256], W2t[NB * 256];
  float ln1g[NB * 8], ln1b[NB * 8], ln2g[NB * 8], ln2b[NB * 8];
  float projb[NB * 8], b1[NB * 32], b2[NB * 8];
  float linW[128];
  float cls[8];
  float pos[TT * 8];
  float mlpW[80], mlpb[12];
};
}  // namespace

typedef unsigned long long u64;

__device__ __forceinline__ u64 pk2(float a, float b) {
  u64 r;
  asm("mov.b64 %0, {%1, %2};" : "=l"(r)
      : "r"(__float_as_uint(a)), "r"(__float_as_uint(b)));
  return r;
}
__device__ __forceinline__ u64 pk1(float a) {
  u64 r;
  asm("mov.b64 %0, {%1, %1};" : "=l"(r) : "r"(__float_as_uint(a)));
  return r;
}
__device__ __forceinline__ void upk2(u64 v, float& a, float& b) {
  unsigned int x, y;
  asm("mov.b64 {%0, %1}, %2;" : "=r"(x), "=r"(y) : "l"(v));
  a = __uint_as_float(x); b = __uint_as_float(y);
}
__device__ __forceinline__ u64 fma2(u64 a, u64 b, u64 c) {
  u64 d;
  asm("fma.rn.f32x2 %0, %1, %2, %3;" : "=l"(d) : "l"(a), "l"(b), "l"(c));
  return d;
}
__device__ __forceinline__ u64 add2(u64 a, u64 b) {
  u64 d;
  asm("add.rn.f32x2 %0, %1, %2;" : "=l"(d) : "l"(a), "l"(b));
  return d;
}
__device__ __forceinline__ u64 mul2(u64 a, u64 b) {
  u64 d;
  asm("mul.rn.f32x2 %0, %1, %2;" : "=l"(d) : "l"(a), "l"(b));
  return d;
}
__device__ __forceinline__ float ex2f(float x) {
  float r;
  asm("ex2.approx.ftz.f32 %0, %1;" : "=f"(r) : "f"(x));
  return r;
}

// load 8-float row (2x LDS.128 broadcast) and pack to {w,w} dup pairs
__device__ __forceinline__ void ldrow8pk(const float* __restrict__ w, u64 wd[8]) {
  float4 w0 = *reinterpret_cast<const float4*>(w);
  float4 w1 = *reinterpret_cast<const float4*>(w + 4);
  wd[0] = pk1(w0.x); wd[1] = pk1(w0.y); wd[2] = pk1(w0.z); wd[3] = pk1(w0.w);
  wd[4] = pk1(w1.x); wd[5] = pk1(w1.y); wd[6] = pk1(w1.z); wd[7] = pk1(w1.w);
}

__device__ __forceinline__ u64 dot8r(const u64 wd[8], const u64 h[8]) {
  u64 s0 = mul2(h[0], wd[0]);
  u64 s1 = mul2(h[1], wd[1]);
  s0 = fma2(h[2], wd[2], s0); s1 = fma2(h[3], wd[3], s1);
  s0 = fma2(h[4], wd[4], s0); s1 = fma2(h[5], wd[5], s1);
  s0 = fma2(h[6], wd[6], s0); s1 = fma2(h[7], wd[7], s1);
  return add2(s0, s1);
}

__device__ __forceinline__ void lnp(const u64 x[8], const u64 g[8],
                                    const u64 b[8], u64 h[8]) {
  u64 s = add2(add2(add2(x[0], x[1]), add2(x[2], x[3])),
               add2(add2(x[4], x[5]), add2(x[6], x[7])));
  float sA, sB;
  upk2(s, sA, sB);
  u64 mu = pk2(sA * 0.125f, sB * 0.125f);
  const u64 N1 = pk1(-1.f);
  u64 c[8];
#pragma unroll
  for (int d = 0; d < 8; d++) c[d] = fma2(mu, N1, x[d]);
  u64 v0 = mul2(c[0], c[0]);
  u64 v1 = mul2(c[1], c[1]);
  v0 = fma2(c[2], c[2], v0); v1 = fma2(c[3], c[3], v1);
  v0 = fma2(c[4], c[4], v0); v1 = fma2(c[5], c[5], v1);
  v0 = fma2(c[6], c[6], v0); v1 = fma2(c[7], c[7], v1);
  float vA, vB;
  upk2(add2(v0, v1), vA, vB);
  u64 rs = pk2(rsqrtf(fmaf(vA, 0.125f, 1e-5f)),
               rsqrtf(fmaf(vB, 0.125f, 1e-5f)));
#pragma unroll
  for (int d = 0; d < 8; d++) h[d] = fma2(mul2(c[d], rs), g[d], b[d]);
}

__global__ void __launch_bounds__(NTH, 2) vit_kernel(
    const float* __restrict__ images, const float* __restrict__ cls_g,
    const float* __restrict__ linW_g, const float* __restrict__ ln1g_g,
    const float* __restrict__ ln1b_g, const float* __restrict__ Wq_g,
    const float* __restrict__ Wk_g, const float* __restrict__ Wv_g,
    const float* __restrict__ projW_g, const float* __restrict__ projb_g,
    const float* __restrict__ ln2g_g, const float* __restrict__ ln2b_g,
    const float* __restrict__ W1_g, const float* __restrict__ b1_g,
    const float* __restrict__ W2_g, const float* __restrict__ b2_g,
    const float* __restrict__ mlpW_g, const float* __restrict__ mlpb_g,
    float* __restrict__ out, int B) {
  extern __shared__ __align__(16) char dsm[];
  u64* skv   = reinterpret_cast<u64*>(dsm);
  u64* stash = skv + KV_U64;
  SW* sw = reinterpret_cast<SW*>(reinterpret_cast<char*>(stash + ST_U64));

  const int tid = threadIdx.x;

  // ---- stage weights (plain fp32, no duplication) ----
  {
    auto cp = [&](float* d, const float* s, int n) {
      for (int i = tid; i < n; i += NTH) d[i] = s[i];
    };
    cp(sw->Wq, Wq_g, NB * 64);   cp(sw->Wk, Wk_g, NB * 64);
    cp(sw->Wv, Wv_g, NB * 64);   cp(sw->projW, projW_g, NB * 64);
    cp(sw->W1, W1_g, NB * 256);
    cp(sw->ln1g, ln1g_g, NB * 8); cp(sw->ln1b, ln1b_g, NB * 8);
    cp(sw->ln2g, ln2g_g, NB * 8); cp(sw->ln2b, ln2b_g, NB * 8);
    cp(sw->projb, projb_g, NB * 8);
    cp(sw->b1, b1_g, NB * 32);    cp(sw->b2, b2_g, NB * 8);
    cp(sw->linW, linW_g, 128);
    cp(sw->cls, cls_g, 8);
    cp(sw->mlpW, mlpW_g, 80);
    for (int i = tid; i < 10; i += NTH) sw->mlpb[i] = mlpb_g[i];
    // W2 [blk][8][32] -> transposed [blk][32][8]
    for (int i = tid; i < NB * 256; i += NTH) {
      int blk = i >> 8, rem = i & 255, f = rem >> 3, d = rem & 7;
      sw->W2t[blk * 256 + rem] = W2_g[blk * 256 + d * 32 + f];
    }
    if (tid < TT) {  // sinusoidal table: freqs {1, .1, .01, .001}
      float tf = (float)tid;
      float* p = sw->pos + tid * 8;
      p[0] = sinf(tf);          p[1] = cosf(tf);
      p[2] = sinf(tf * 0.1f);   p[3] = cosf(tf * 0.1f);
      p[4] = sinf(tf * 0.01f);  p[5] = cosf(tf * 0.01f);
      p[6] = sinf(tf * 0.001f); p[7] = cosf(tf * 0.001f);
    }
  }
  __syncthreads();

  const int warp = tid >> 5;
  const int lane = tid & 31;
  const bool act = (lane < 25);
  const int t0 = lane;
  const int t1 = lane + 25;
  const int gb0 = (blockIdx.x * WPC + warp) * 2;
  const int gb1 = gb0 + 1;

  u64* kvb = skv + warp * (TT * ROW);
  u64* xs  = stash + (warp * 25 + lane) * ST_STR;  // 16 u64 per thread

  u64 X0[8], X1[8];  // token t0, t1 activations ({imgA,imgB} pairs)

  // ---- patch embed + positional (cold path, scalar fp32) ----
  if (act) {
    auto embed_tok = [&](int t, u64 xr[8]) {
      if (t == 0) {
#pragma unroll
        for (int d = 0; d < 8; d++) {
          float v = sw->cls[d] + sw->pos[d];
          xr[d] = pk1(v);
        }
        return;
      }
      int p = t - 1, r = p / 7, c = p % 7;
      float eo[2][8];
#pragma unroll
      for (int img = 0; img < 2; img++) {
        int gb = gb0 + img;
        float px[16];
        if (gb < B) {
          const float* ip = images + (size_t)gb * 784 + (r * 4) * 28 + c * 4;
#pragma unroll
          for (int i = 0; i < 4; i++) {
            float4 v4 = *reinterpret_cast<const float4*>(ip + i * 28);
            px[4 * i] = v4.x; px[4 * i + 1] = v4.y;
            px[4 * i + 2] = v4.z; px[4 * i + 3] = v4.w;
          }
        } else {
#pragma unroll
          for (int j = 0; j < 16; j++) px[j] = 0.f;
        }
#pragma unroll
        for (int d = 0; d < 8; d++) {
          const float* w = sw->linW + d * 16;
          float s = 0.f;
#pragma unroll
          for (int j = 0; j < 16; j++) s = fmaf(px[j], w[j], s);
          eo[img][d] = s + sw->pos[t * 8 + d];
        }
      }
#pragma unroll
      for (int d = 0; d < 8; d++) xr[d] = pk2(eo[0][d], eo[1][d]);
    };
    embed_tok(t0, X0);
    embed_tok(t1, X1);
  }

  // scale * log2(e): softmax in base 2
  const float SCL2E = 0.35355339059327373f * 1.4426950408889634f;

#pragma unroll 1
  for (int blk = 0; blk < NB; blk++) {
    u64 Q0[8], Q1[8];
    if (act) {
      // LN1 (packed gamma/beta shared across both tokens)
      u64 gp[8], bp[8], H0[8], H1[8];
      ldrow8pk(sw->ln1g + blk * 8, gp);
      ldrow8pk(sw->ln1b + blk * 8, bp);
      lnp(X0, gp, bp, H0);
      lnp(X1, gp, bp, H1);
      // stash X (dead until proj residual)
      {
        ulonglong2* s2 = reinterpret_cast<ulonglong2*>(xs);
#pragma unroll
        for (int i = 0; i < 4; i++)
          s2[i] = make_ulonglong2(X0[2 * i], X0[2 * i + 1]);
#pragma unroll
        for (int i = 0; i < 4; i++)
          s2[4 + i] = make_ulonglong2(X1[2 * i], X1[2 * i + 1]);
      }
      const u64 SC2 = pk1(SCL2E);
      u64 wd[8];
      const float* wq = sw->Wq + blk * 64;
#pragma unroll
      for (int e = 0; e < 8; e++) {
        ldrow8pk(wq + e * 8, wd);
        Q0[e] = mul2(dot8r(wd, H0), SC2);
        Q1[e] = mul2(dot8r(wd, H1), SC2);
      }
      const float* wk = sw->Wk + blk * 64;
      u64* kr0 = kvb + t0 * ROW;
      u64* kr1 = kvb + t1 * ROW;
#pragma unroll
      for (int e = 0; e < 8; e++) {
        ldrow8pk(wk + e * 8, wd);
        kr0[e] = dot8r(wd, H0);
        kr1[e] = dot8r(wd, H1);
      }
      const float* wv = sw->Wv + blk * 64;
#pragma unroll
      for (int e = 0; e < 8; e++) {
        ldrow8pk(wv + e * 8, wd);
        kr0[VOFF + e] = dot8r(wd, H0);
        kr1[VOFF + e] = dot8r(wd, H1);
      }
    }
    __syncthreads();

    u64 O0[8], O1[8];
    if (act) {
      // base-2 no-max softmax; 4 independent (token,head) chains x 2 images
      u64 l00 = 0, l01 = 0, l10 = 0, l11 = 0;
      u64 a0[8], a1[8];
#pragma unroll
      for (int j = 0; j < 8; j++) { a0[j] = 0; a1[j] = 0; }
#pragma unroll 1
      for (int u = 0; u < TT; u++) {
        const ulonglong2* kp =
            reinterpret_cast<const ulonglong2*>(kvb + u * ROW);
        ulonglong2 k0 = kp[0], k1 = kp[1], k2 = kp[2], k3 = kp[3];
        // scores tok0
        u64 s00 = fma2(Q0[0], k0.x,
                  fma2(Q0[1], k0.y, fma2(Q0[2], k1.x, mul2(Q0[3], k1.y))));
        u64 s01 = fma2(Q0[4], k2.x,
                  fma2(Q0[5], k2.y, fma2(Q0[6], k3.x, mul2(Q0[7], k3.y))));
        // scores tok1
        u64 s10 = fma2(Q1[0], k0.x,
                  fma2(Q1[1], k0.y, fma2(Q1[2], k1.x, mul2(Q1[3], k1.y))));
        u64 s11 = fma2(Q1[4], k2.x,
                  fma2(Q1[5], k2.y, fma2(Q1[6], k3.x, mul2(Q1[7], k3.y))));
        const ulonglong2* vp =
            reinterpret_cast<const ulonglong2*>(kvb + u * ROW + VOFF);
        ulonglong2 v0 = vp[0], v1 = vp[1], v2 = vp[2], v3 = vp[3];
        float xa, xb;
        upk2(s00, xa, xb);
        u64 p00 = pk2(ex2f(xa), ex2f(xb));
        upk2(s01, xa, xb);
        u64 p01 = pk2(ex2f(xa), ex2f(xb));
        upk2(s10, xa, xb);
        u64 p10 = pk2(ex2f(xa), ex2f(xb));
        upk2(s11, xa, xb);
        u64 p11 = pk2(ex2f(xa), ex2f(xb));
        l00 = add2(l00, p00); l01 = add2(l01, p01);
        l10 = add2(l10, p10); l11 = add2(l11, p11);
        a0[0] = fma2(p00, v0.x, a0[0]); a0[1] = fma2(p00, v0.y, a0[1]);
        a0[2] = fma2(p00, v1.x, a0[2]); a0[3] = fma2(p00, v1.y, a0[3]);
        a0[4] = fma2(p01, v2.x, a0[4]); a0[5] = fma2(p01, v2.y, a0[5]);
        a0[6] = fma2(p01, v3.x, a0[6]); a0[7] = fma2(p01, v3.y, a0[7]);
        a1[0] = fma2(p10, v0.x, a1[0]); a1[1] = fma2(p10, v0.y, a1[1]);
        a1[2] = fma2(p10, v1.x, a1[2]); a1[3] = fma2(p10, v1.y, a1[3]);
        a1[4] = fma2(p11, v2.x, a1[4]); a1[5] = fma2(p11, v2.y, a1[5]);
        a1[6] = fma2(p11, v3.x, a1[6]); a1[7] = fma2(p11, v3.y, a1[7]);
      }
      float lA, lB;
      upk2(l00, lA, lB);
      u64 i00 = pk2(1.f / lA, 1.f / lB);
      upk2(l01, lA, lB);
      u64 i01 = pk2(1.f / lA, 1.f / lB);
      upk2(l10, lA, lB);
      u64 i10 = pk2(1.f / lA, 1.f / lB);
      upk2(l11, lA, lB);
      u64 i11 = pk2(1.f / lA, 1.f / lB);
#pragma unroll
      for (int j = 0; j < 4; j++) {
        O0[j] = mul2(a0[j], i00);
        O0[4 + j] = mul2(a0[4 + j], i01);
        O1[j] = mul2(a1[j], i10);
        O1[4 + j] = mul2(a1[4 + j], i11);
      }
    }
    __syncthreads();  // kv consumed; next block may overwrite

    if (act) {
      // reload X, proj + residual
      {
        const ulonglong2* s2 = reinterpret_cast<const ulonglong2*>(xs);
#pragma unroll
        for (int i = 0; i < 4; i++) {
          ulonglong2 v = s2[i];
          X0[2 * i] = v.x; X0[2 * i + 1] = v.y;
        }
#pragma unroll
        for (int i = 0; i < 4; i++) {
          ulonglong2 v = s2[4 + i];
          X1[2 * i] = v.x; X1[2 * i + 1] = v.y;
        }
      }
      u64 wd[8], pbp[8];
      ldrow8pk(sw->projb + blk * 8, pbp);
      const float* pw = sw->projW + blk * 64;
#pragma unroll
      for (int e = 0; e < 8; e++) {
        ldrow8pk(pw + e * 8, wd);
        X0[e] = add2(X0[e], add2(dot8r(wd, O0), pbp[e]));
        X1[e] = add2(X1[e], add2(dot8r(wd, O1), pbp[e]));
      }

      // LN2
      u64 gp[8], bp[8], H0[8], H1[8];
      ldrow8pk(sw->ln2g + blk * 8, gp);
      ldrow8pk(sw->ln2b + blk * 8, bp);
      lnp(X0, gp, bp, H0);
      lnp(X1, gp, bp, H1);
      // stash X again (dead during MLP)
      {
        ulonglong2* s2 = reinterpret_cast<ulonglong2*>(xs);
#pragma unroll
        for (int i = 0; i < 4; i++)
          s2[i] = make_ulonglong2(X0[2 * i], X0[2 * i + 1]);
#pragma unroll
        for (int i = 0; i < 4; i++)
          s2[4 + i] = make_ulonglong2(X1[2 * i], X1[2 * i + 1]);
      }

      // MLP 8 -> 32 (relu) -> 8
      const float* w1 = sw->W1 + blk * 256;
      const float* b1 = sw->b1 + blk * 32;
      const float* w2 = sw->W2t + blk * 256;
      u64 acc0[8], acc1[8];
#pragma unroll
      for (int d = 0; d < 8; d++) { acc0[d] = 0; acc1[d] = 0; }
#pragma unroll 2
      for (int f = 0; f < 32; f++) {
        ldrow8pk(w1 + f * 8, wd);
        u64 bf = pk1(b1[f]);
        u64 f0 = add2(dot8r(wd, H0), bf);
        u64 f1 = add2(dot8r(wd, H1), bf);
        float fa, fb;
        upk2(f0, fa, fb);
        f0 = pk2(fmaxf(fa, 0.f), fmaxf(fb, 0.f));
        upk2(f1, fa, fb);
        f1 = pk2(fmaxf(fa, 0.f), fmaxf(fb, 0.f));
        ldrow8pk(w2 + f * 8, wd);
#pragma unroll
        for (int d = 0; d < 8; d++) {
          acc0[d] = fma2(f0, wd[d], acc0[d]);
          acc1[d] = fma2(f1, wd[d], acc1[d]);
        }
      }
      // reload X, final residual
      u64 b2p[8];
      ldrow8pk(sw->b2 + blk * 8, b2p);
      {
        const ulonglong2* s2 = reinterpret_cast<const ulonglong2*>(xs);
#pragma unroll
        for (int i = 0; i < 4; i++) {
          ulonglong2 v = s2[i];
          X0[2 * i] = v.x; X0[2 * i + 1] = v.y;
        }
#pragma unroll
        for (int i = 0; i < 4; i++) {
          ulonglong2 v = s2[4 + i];
          X1[2 * i] = v.x; X1[2 * i + 1] = v.y;
        }
      }
#pragma unroll
      for (int d = 0; d < 8; d++) {
        X0[d] = add2(X0[d], add2(acc0[d], b2p[d]));
        X1[d] = add2(X1[d], add2(acc1[d], b2p[d]));
      }
    }
  }

  // classification head on token 0 (lane 0's t0): softmax(x0 @ mlpW^T + mlpb)
  if (act && lane == 0) {
    float xA[8], xB[8];
#pragma unroll
    for (int d = 0; d < 8; d++) upk2(X0[d], xA[d], xB[d]);
    auto head = [&](const float x[8], int gb) {
      if (gb >= B) return;
      float z[10];
      float zm = -1e30f;
#pragma unroll
      for (int c = 0; c < 10; c++) {
        const float* w = sw->mlpW + c * 8;
        float s = sw->mlpb[c];
#pragma unroll
        for (int j = 0; j < 8; j++) s = fmaf(x[j], w[j], s);
        z[c] = s;
        zm = fmaxf(zm, s);
      }
      float ssum = 0.f;
#pragma unroll
      for (int c = 0; c < 10; c++) { z[c] = __expf(z[c] - zm); ssum += z[c]; }
      float inv = 1.f / ssum;
#pragma unroll
      for (int c = 0; c < 10; c++) out[gb * 10 + c] = z[c] * inv;
    };
    head(xA, gb0);
    head(xB, gb1);
  }
}

extern "C" void kernel_launch(void* const* d_in, const int* in_sizes, int n_in,
                              void* d_out, int out_size) {
  const float* images = (const float*)d_in[0];
  const float* cls    = (const float*)d_in[1];
  const float* linW   = (const float*)d_in[2];
  const float* ln1g   = (const float*)d_in[3];
  const float* ln1b   = (const float*)d_in[4];
  const float* Wq     = (const float*)d_in[5];
  const float* Wk     = (const float*)d_in[6];
  const float* Wv     = (const float*)d_in[7];
  const float* projW  = (const float*)d_in[8];
  const float* projb  = (const float*)d_in[9];
  const float* ln2g   = (const float*)d_in[10];
  const float* ln2b   = (const float*)d_in[11];
  const float* W1     = (const float*)d_in[12];
  const float* b1     = (const float*)d_in[13];
  const float* W2     = (const float*)d_in[14];
  const float* b2     = (const float*)d_in[15];
  const float* mlpW   = (const float*)d_in[16];
  const float* mlpb   = (const float*)d_in[17];

  int B = in_sizes[0] / 784;
  int smem = (KV_U64 + ST_U64) * 8 + (int)sizeof(SW);
  cudaFuncSetAttribute(vit_kernel, cudaFuncAttributeMaxDynamicSharedMemorySize,
                       smem);
  dim3 grid((B + IPC - 1) / IPC);
  vit_kernel<<<grid, NTH, smem>>>(images, cls, linW, ln1g, ln1b, Wq, Wk, Wv,
                                  projW, projb, ln2g, ln2b, W1, b1, W2, b2,
                                  mlpW, mlpb, (float*)d_out, B);
}

// round 8
// speedup vs baseline: 1.5683x; 1.0419x over previous
#include <cuda_runtime.h>

// Tiny-ViT fused forward, round 7: R5 + head-split attention.
//  - attention runs as TWO sequential per-head passes: each pass loads only
//    that head's K/V halves (4 LDS.128/u, same total as before) but the live
//    register set halves -> un-pins regs from the 128 cap (no spill), lets
//    ptxas pipeline unroll-2 iterations.
//  - 2 tokens x 2 images per thread; de-dup fp32 weights; f32x2 math;
//    base-2 no-max softmax; X stashed to smem in dead phases.
// CTA: 256 threads = 8 warps = 8 slots = 16 images. grid = B/16.

namespace {
constexpr int NB  = 4;
constexpr int TT  = 50;
constexpr int NTH = 256;
constexpr int WPC = 8;     // warps (slots) per CTA
constexpr int IPC = 16;    // images per CTA
constexpr int ROW  = 18;   // u64 per kv token row (144B: k[0..7], pad, v[10..17])
constexpr int VOFF = 10;
constexpr int KV_U64 = WPC * TT * ROW;        // 7200
constexpr int ST_STR = 18;                    // stash stride (u64)
constexpr int ST_U64 = WPC * 25 * ST_STR;     // 3600

struct SW {  // de-duplicated fp32 weights
  float Wq[NB * 64], Wk[NB * 64], Wv[NB * 64], projW[NB * 64];
  float W1[NB * 256], W2t[NB * 256];
  float ln1g[NB * 8], ln1b[NB * 8], ln2g[NB * 8], ln2b[NB * 8];
  float projb[NB * 8], b1[NB * 32], b2[NB * 8];
  float linW[128];
  float cls[8];
  float pos[TT * 8];
  float mlpW[80], mlpb[12];
};
}  // namespace

typedef unsigned long long u64;

__device__ __forceinline__ u64 pk2(float a, float b) {
  u64 r;
  asm("mov.b64 %0, {%1, %2};" : "=l"(r)
      : "r"(__float_as_uint(a)), "r"(__float_as_uint(b)));
  return r;
}
__device__ __forceinline__ u64 pk1(float a) {
  u64 r;
  asm("mov.b64 %0, {%1, %1};" : "=l"(r) : "r"(__float_as_uint(a)));
  return r;
}
__device__ __forceinline__ void upk2(u64 v, float& a, float& b) {
  unsigned int x, y;
  asm("mov.b64 {%0, %1}, %2;" : "=r"(x), "=r"(y) : "l"(v));
  a = __uint_as_float(x); b = __uint_as_float(y);
}
__device__ __forceinline__ u64 fma2(u64 a, u64 b, u64 c) {
  u64 d;
  asm("fma.rn.f32x2 %0, %1, %2, %3;" : "=l"(d) : "l"(a), "l"(b), "l"(c));
  return d;
}
__device__ __forceinline__ u64 add2(u64 a, u64 b) {
  u64 d;
  asm("add.rn.f32x2 %0, %1, %2;" : "=l"(d) : "l"(a), "l"(b));
  return d;
}
__device__ __forceinline__ u64 mul2(u64 a, u64 b) {
  u64 d;
  asm("mul.rn.f32x2 %0, %1, %2;" : "=l"(d) : "l"(a), "l"(b));
  return d;
}
__device__ __forceinline__ float ex2f(float x) {
  float r;
  asm("ex2.approx.ftz.f32 %0, %1;" : "=f"(r) : "f"(x));
  return r;
}

// load 8-float row (2x LDS.128 broadcast) and pack to {w,w} dup pairs
__device__ __forceinline__ void ldrow8pk(const float* __restrict__ w, u64 wd[8]) {
  float4 w0 = *reinterpret_cast<const float4*>(w);
  float4 w1 = *reinterpret_cast<const float4*>(w + 4);
  wd[0] = pk1(w0.x); wd[1] = pk1(w0.y); wd[2] = pk1(w0.z); wd[3] = pk1(w0.w);
  wd[4] = pk1(w1.x); wd[5] = pk1(w1.y); wd[6] = pk1(w1.z); wd[7] = pk1(w1.w);
}

__device__ __forceinline__ u64 dot8r(const u64 wd[8], const u64 h[8]) {
  u64 s0 = mul2(h[0], wd[0]);
  u64 s1 = mul2(h[1], wd[1]);
  s0 = fma2(h[2], wd[2], s0); s1 = fma2(h[3], wd[3], s1);
  s0 = fma2(h[4], wd[4], s0); s1 = fma2(h[5], wd[5], s1);
  s0 = fma2(h[6], wd[6], s0); s1 = fma2(h[7], wd[7], s1);
  return add2(s0, s1);
}

__device__ __forceinline__ void lnp(const u64 x[8], const u64 g[8],
                                    const u64 b[8], u64 h[8]) {
  u64 s = add2(add2(add2(x[0], x[1]), add2(x[2], x[3])),
               add2(add2(x[4], x[5]), add2(x[6], x[7])));
  float sA, sB;
  upk2(s, sA, sB);
  u64 mu = pk2(sA * 0.125f, sB * 0.125f);
  const u64 N1 = pk1(-1.f);
  u64 c[8];
#pragma unroll
  for (int d = 0; d < 8; d++) c[d] = fma2(mu, N1, x[d]);
  u64 v0 = mul2(c[0], c[0]);
  u64 v1 = mul2(c[1], c[1]);
  v0 = fma2(c[2], c[2], v0); v1 = fma2(c[3], c[3], v1);
  v0 = fma2(c[4], c[4], v0); v1 = fma2(c[5], c[5], v1);
  v0 = fma2(c[6], c[6], v0); v1 = fma2(c[7], c[7], v1);
  float vA, vB;
  upk2(add2(v0, v1), vA, vB);
  u64 rs = pk2(rsqrtf(fmaf(vA, 0.125f, 1e-5f)),
               rsqrtf(fmaf(vB, 0.125f, 1e-5f)));
#pragma unroll
  for (int d = 0; d < 8; d++) h[d] = fma2(mul2(c[d], rs), g[d], b[d]);
}

__global__ void __launch_bounds__(NTH, 2) vit_kernel(
    const float* __restrict__ images, const float* __restrict__ cls_g,
    const float* __restrict__ linW_g, const float* __restrict__ ln1g_g,
    const float* __restrict__ ln1b_g, const float* __restrict__ Wq_g,
    const float* __restrict__ Wk_g, const float* __restrict__ Wv_g,
    const float* __restrict__ projW_g, const float* __restrict__ projb_g,
    const float* __restrict__ ln2g_g, const float* __restrict__ ln2b_g,
    const float* __restrict__ W1_g, const float* __restrict__ b1_g,
    const float* __restrict__ W2_g, const float* __restrict__ b2_g,
    const float* __restrict__ mlpW_g, const float* __restrict__ mlpb_g,
    float* __restrict__ out, int B) {
  extern __shared__ __align__(16) char dsm[];
  u64* skv   = reinterpret_cast<u64*>(dsm);
  u64* stash = skv + KV_U64;
  SW* sw = reinterpret_cast<SW*>(reinterpret_cast<char*>(stash + ST_U64));

  const int tid = threadIdx.x;

  // ---- stage weights (plain fp32, no duplication) ----
  {
    auto cp = [&](float* d, const float* s, int n) {
      for (int i = tid; i < n; i += NTH) d[i] = s[i];
    };
    cp(sw->Wq, Wq_g, NB * 64);   cp(sw->Wk, Wk_g, NB * 64);
    cp(sw->Wv, Wv_g, NB * 64);   cp(sw->projW, projW_g, NB * 64);
    cp(sw->W1, W1_g, NB * 256);
    cp(sw->ln1g, ln1g_g, NB * 8); cp(sw->ln1b, ln1b_g, NB * 8);
    cp(sw->ln2g, ln2g_g, NB * 8); cp(sw->ln2b, ln2b_g, NB * 8);
    cp(sw->projb, projb_g, NB * 8);
    cp(sw->b1, b1_g, NB * 32);    cp(sw->b2, b2_g, NB * 8);
    cp(sw->linW, linW_g, 128);
    cp(sw->cls, cls_g, 8);
    cp(sw->mlpW, mlpW_g, 80);
    for (int i = tid; i < 10; i += NTH) sw->mlpb[i] = mlpb_g[i];
    // W2 [blk][8][32] -> transposed [blk][32][8]
    for (int i = tid; i < NB * 256; i += NTH) {
      int blk = i >> 8, rem = i & 255, f = rem >> 3, d = rem & 7;
      sw->W2t[blk * 256 + rem] = W2_g[blk * 256 + d * 32 + f];
    }
    if (tid < TT) {  // sinusoidal table: freqs {1, .1, .01, .001}
      float tf = (float)tid;
      float* p = sw->pos + tid * 8;
      p[0] = sinf(tf);          p[1] = cosf(tf);
      p[2] = sinf(tf * 0.1f);   p[3] = cosf(tf * 0.1f);
      p[4] = sinf(tf * 0.01f);  p[5] = cosf(tf * 0.01f);
      p[6] = sinf(tf * 0.001f); p[7] = cosf(tf * 0.001f);
    }
  }
  __syncthreads();

  const int warp = tid >> 5;
  const int lane = tid & 31;
  const bool act = (lane < 25);
  const int t0 = lane;
  const int t1 = lane + 25;
  const int gb0 = (blockIdx.x * WPC + warp) * 2;
  const int gb1 = gb0 + 1;

  u64* kvb = skv + warp * (TT * ROW);
  u64* xs  = stash + (warp * 25 + lane) * ST_STR;  // 16 u64 per thread

  u64 X0[8], X1[8];  // token t0, t1 activations ({imgA,imgB} pairs)

  // ---- patch embed + positional (cold path, scalar fp32) ----
  if (act) {
    auto embed_tok = [&](int t, u64 xr[8]) {
      if (t == 0) {
#pragma unroll
        for (int d = 0; d < 8; d++) {
          float v = sw->cls[d] + sw->pos[d];
          xr[d] = pk1(v);
        }
        return;
      }
      int p = t - 1, r = p / 7, c = p % 7;
      float eo[2][8];
#pragma unroll
      for (int img = 0; img < 2; img++) {
        int gb = gb0 + img;
        float px[16];
        if (gb < B) {
          const float* ip = images + (size_t)gb * 784 + (r * 4) * 28 + c * 4;
#pragma unroll
          for (int i = 0; i < 4; i++) {
            float4 v4 = *reinterpret_cast<const float4*>(ip + i * 28);
            px[4 * i] = v4.x; px[4 * i + 1] = v4.y;
            px[4 * i + 2] = v4.z; px[4 * i + 3] = v4.w;
          }
        } else {
#pragma unroll
          for (int j = 0; j < 16; j++) px[j] = 0.f;
        }
#pragma unroll
        for (int d = 0; d < 8; d++) {
          const float* w = sw->linW + d * 16;
          float s = 0.f;
#pragma unroll
          for (int j = 0; j < 16; j++) s = fmaf(px[j], w[j], s);
          eo[img][d] = s + sw->pos[t * 8 + d];
        }
      }
#pragma unroll
      for (int d = 0; d < 8; d++) xr[d] = pk2(eo[0][d], eo[1][d]);
    };
    embed_tok(t0, X0);
    embed_tok(t1, X1);
  }

  // scale * log2(e): softmax in base 2
  const float SCL2E = 0.35355339059327373f * 1.4426950408889634f;

#pragma unroll 1
  for (int blk = 0; blk < NB; blk++) {
    u64 Q0[8], Q1[8];
    if (act) {
      // LN1 (packed gamma/beta shared across both tokens)
      u64 gp[8], bp[8], H0[8], H1[8];
      ldrow8pk(sw->ln1g + blk * 8, gp);
      ldrow8pk(sw->ln1b + blk * 8, bp);
      lnp(X0, gp, bp, H0);
      lnp(X1, gp, bp, H1);
      // stash X (dead until proj residual)
      {
        ulonglong2* s2 = reinterpret_cast<ulonglong2*>(xs);
#pragma unroll
        for (int i = 0; i < 4; i++)
          s2[i] = make_ulonglong2(X0[2 * i], X0[2 * i + 1]);
#pragma unroll
        for (int i = 0; i < 4; i++)
          s2[4 + i] = make_ulonglong2(X1[2 * i], X1[2 * i + 1]);
      }
      const u64 SC2 = pk1(SCL2E);
      u64 wd[8];
      const float* wq = sw->Wq + blk * 64;
#pragma unroll
      for (int e = 0; e < 8; e++) {
        ldrow8pk(wq + e * 8, wd);
        Q0[e] = mul2(dot8r(wd, H0), SC2);
        Q1[e] = mul2(dot8r(wd, H1), SC2);
      }
      const float* wk = sw->Wk + blk * 64;
      u64* kr0 = kvb + t0 * ROW;
      u64* kr1 = kvb + t1 * ROW;
#pragma unroll
      for (int e = 0; e < 8; e++) {
        ldrow8pk(wk + e * 8, wd);
        kr0[e] = dot8r(wd, H0);
        kr1[e] = dot8r(wd, H1);
      }
      const float* wv = sw->Wv + blk * 64;
#pragma unroll
      for (int e = 0; e < 8; e++) {
        ldrow8pk(wv + e * 8, wd);
        kr0[VOFF + e] = dot8r(wd, H0);
        kr1[VOFF + e] = dot8r(wd, H1);
      }
    }
    __syncthreads();

    u64 O0[8], O1[8];
    if (act) {
      // base-2 no-max softmax, TWO sequential per-head passes.
      // Each pass: 4 LDS.128 per u (that head's K half + V half); live set
      // per pass = 8 Q-halves + 8 acc + 2 sums (vs 16 Q + 16 acc fused).
#pragma unroll 1
      for (int h = 0; h < 2; h++) {
        const u64 q00 = Q0[4 * h + 0], q01 = Q0[4 * h + 1];
        const u64 q02 = Q0[4 * h + 2], q03 = Q0[4 * h + 3];
        const u64 q10 = Q1[4 * h + 0], q11 = Q1[4 * h + 1];
        const u64 q12 = Q1[4 * h + 2], q13 = Q1[4 * h + 3];
        const u64* kh = kvb + 4 * h;
        const u64* vh = kvb + VOFF + 4 * h;
        u64 l0 = 0, l1 = 0;
        u64 a00 = 0, a01 = 0, a02 = 0, a03 = 0;
        u64 a10 = 0, a11 = 0, a12 = 0, a13 = 0;
#pragma unroll 2
        for (int u = 0; u < TT; u++) {
          const ulonglong2* kp =
              reinterpret_cast<const ulonglong2*>(kh + u * ROW);
          ulonglong2 k0 = kp[0], k1 = kp[1];
          const ulonglong2* vp =
              reinterpret_cast<const ulonglong2*>(vh + u * ROW);
          ulonglong2 v0 = vp[0], v1 = vp[1];
          u64 s0 = fma2(q00, k0.x,
                   fma2(q01, k0.y, fma2(q02, k1.x, mul2(q03, k1.y))));
          u64 s1 = fma2(q10, k0.x,
                   fma2(q11, k0.y, fma2(q12, k1.x, mul2(q13, k1.y))));
          float xa, xb;
          upk2(s0, xa, xb);
          u64 p0 = pk2(ex2f(xa), ex2f(xb));
          upk2(s1, xa, xb);
          u64 p1 = pk2(ex2f(xa), ex2f(xb));
          l0 = add2(l0, p0);
          l1 = add2(l1, p1);
          a00 = fma2(p0, v0.x, a00); a01 = fma2(p0, v0.y, a01);
          a02 = fma2(p0, v1.x, a02); a03 = fma2(p0, v1.y, a03);
          a10 = fma2(p1, v0.x, a10); a11 = fma2(p1, v0.y, a11);
          a12 = fma2(p1, v1.x, a12); a13 = fma2(p1, v1.y, a13);
        }
        float lA, lB;
        upk2(l0, lA, lB);
        u64 i0 = pk2(1.f / lA, 1.f / lB);
        upk2(l1, lA, lB);
        u64 i1 = pk2(1.f / lA, 1.f / lB);
        O0[4 * h + 0] = mul2(a00, i0); O0[4 * h + 1] = mul2(a01, i0);
        O0[4 * h + 2] = mul2(a02, i0); O0[4 * h + 3] = mul2(a03, i0);
        O1[4 * h + 0] = mul2(a10, i1); O1[4 * h + 1] = mul2(a11, i1);
        O1[4 * h + 2] = mul2(a12, i1); O1[4 * h + 3] = mul2(a13, i1);
      }
    }
    __syncthreads();  // kv consumed; next block may overwrite

    if (act) {
      // reload X, proj + residual
      {
        const ulonglong2* s2 = reinterpret_cast<const ulonglong2*>(xs);
#pragma unroll
        for (int i = 0; i < 4; i++) {
          ulonglong2 v = s2[i];
          X0[2 * i] = v.x; X0[2 * i + 1] = v.y;
        }
#pragma unroll
        for (int i = 0; i < 4; i++) {
          ulonglong2 v = s2[4 + i];
          X1[2 * i] = v.x; X1[2 * i + 1] = v.y;
        }
      }
      u64 wd[8], pbp[8];
      ldrow8pk(sw->projb + blk * 8, pbp);
      const float* pw = sw->projW + blk * 64;
#pragma unroll
      for (int e = 0; e < 8; e++) {
        ldrow8pk(pw + e * 8, wd);
        X0[e] = add2(X0[e], add2(dot8r(wd, O0), pbp[e]));
        X1[e] = add2(X1[e], add2(dot8r(wd, O1), pbp[e]));
      }

      // LN2
      u64 gp[8], bp[8], H0[8], H1[8];
      ldrow8pk(sw->ln2g + blk * 8, gp);
      ldrow8pk(sw->ln2b + blk * 8, bp);
      lnp(X0, gp, bp, H0);
      lnp(X1, gp, bp, H1);
      // stash X again (dead during MLP)
      {
        ulonglong2* s2 = reinterpret_cast<ulonglong2*>(xs);
#pragma unroll
        for (int i = 0; i < 4; i++)
          s2[i] = make_ulonglong2(X0[2 * i], X0[2 * i + 1]);
#pragma unroll
        for (int i = 0; i < 4; i++)
          s2[4 + i] = make_ulonglong2(X1[2 * i], X1[2 * i + 1]);
      }

      // MLP 8 -> 32 (relu) -> 8
      const float* w1 = sw->W1 + blk * 256;
      const float* b1 = sw->b1 + blk * 32;
      const float* w2 = sw->W2t + blk * 256;
      u64 acc0[8], acc1[8];
#pragma unroll
      for (int d = 0; d < 8; d++) { acc0[d] = 0; acc1[d] = 0; }
#pragma unroll 4
      for (int f = 0; f < 32; f++) {
        u64 wd2[8];
        ldrow8pk(w1 + f * 8, wd2);
        u64 bf = pk1(b1[f]);
        u64 f0 = add2(dot8r(wd2, H0), bf);
        u64 f1 = add2(dot8r(wd2, H1), bf);
        float fa, fb;
        upk2(f0, fa, fb);
        f0 = pk2(fmaxf(fa, 0.f), fmaxf(fb, 0.f));
        upk2(f1, fa, fb);
        f1 = pk2(fmaxf(fa, 0.f), fmaxf(fb, 0.f));
        ldrow8pk(w2 + f * 8, wd2);
#pragma unroll
        for (int d = 0; d < 8; d++) {
          acc0[d] = fma2(f0, wd2[d], acc0[d]);
          acc1[d] = fma2(f1, wd2[d], acc1[d]);
        }
      }
      // reload X, final residual
      u64 b2p[8];
      ldrow8pk(sw->b2 + blk * 8, b2p);
      {
        const ulonglong2* s2 = reinterpret_cast<const ulonglong2*>(xs);
#pragma unroll
        for (int i = 0; i < 4; i++) {
          ulonglong2 v = s2[i];
          X0[2 * i] = v.x; X0[2 * i + 1] = v.y;
        }
#pragma unroll
        for (int i = 0; i < 4; i++) {
          ulonglong2 v = s2[4 + i];
          X1[2 * i] = v.x; X1[2 * i + 1] = v.y;
        }
      }
#pragma unroll
      for (int d = 0; d < 8; d++) {
        X0[d] = add2(X0[d], add2(acc0[d], b2p[d]));
        X1[d] = add2(X1[d], add2(acc1[d], b2p[d]));
      }
    }
  }

  // classification head on token 0 (lane 0's t0): softmax(x0 @ mlpW^T + mlpb)
  if (act && lane == 0) {
    float xA[8], xB[8];
#pragma unroll
    for (int d = 0; d < 8; d++) upk2(X0[d], xA[d], xB[d]);
    auto head = [&](const float x[8], int gb) {
      if (gb >= B) return;
      float z[10];
      float zm = -1e30f;
#pragma unroll
      for (int c = 0; c < 10; c++) {
        const float* w = sw->mlpW + c * 8;
        float s = sw->mlpb[c];
#pragma unroll
        for (int j = 0; j < 8; j++) s = fmaf(x[j], w[j], s);
        z[c] = s;
        zm = fmaxf(zm, s);
      }
      float ssum = 0.f;
#pragma unroll
      for (int c = 0; c < 10; c++) { z[c] = __expf(z[c] - zm); ssum += z[c]; }
      float inv = 1.f / ssum;
#pragma unroll
      for (int c = 0; c < 10; c++) out[gb * 10 + c] = z[c] * inv;
    };
    head(xA, gb0);
    head(xB, gb1);
  }
}

extern "C" void kernel_launch(void* const* d_in, const int* in_sizes, int n_in,
                              void* d_out, int out_size) {
  const float* images = (const float*)d_in[0];
  const float* cls    = (const float*)d_in[1];
  const float* linW   = (const float*)d_in[2];
  const float* ln1g   = (const float*)d_in[3];
  const float* ln1b   = (const float*)d_in[4];
  const float* Wq     = (const float*)d_in[5];
  const float* Wk     = (const float*)d_in[6];
  const float* Wv     = (const float*)d_in[7];
  const float* projW  = (const float*)d_in[8];
  const float* projb  = (const float*)d_in[9];
  const float* ln2g   = (const float*)d_in[10];
  const float* ln2b   = (const float*)d_in[11];
  const float* W1     = (const float*)d_in[12];
  const float* b1     = (const float*)d_in[13];
  const float* W2     = (const float*)d_in[14];
  const float* b2     = (const float*)d_in[15];
  const float* mlpW   = (const float*)d_in[16];
  const float* mlpb   = (const float*)d_in[17];

  int B = in_sizes[0] / 784;
  int smem = (KV_U64 + ST_U64) * 8 + (int)sizeof(SW);
  cudaFuncSetAttribute(vit_kernel, cudaFuncAttributeMaxDynamicSharedMemorySize,
                       smem);
  dim3 grid((B + IPC - 1) / IPC);
  vit_kernel<<<grid, NTH, smem>>>(images, cls, linW, ln1g, ln1b, Wq, Wk, Wv,
                                  projW, projb, ln2g, ln2b, W1, b1, W2, b2,
                                  mlpW, mlpb, (float*)d_out, B);
}

// round 9
// speedup vs baseline: 1.5688x; 1.0003x over previous
#include <cuda_runtime.h>

// Tiny-ViT fused forward, round 7: R5 + head-split attention.
//  - attention runs as TWO sequential per-head passes: each pass loads only
//    that head's K/V halves (4 LDS.128/u, same total as before) but the live
//    register set halves -> un-pins regs from the 128 cap (no spill), lets
//    ptxas pipeline unroll-2 iterations.
//  - 2 tokens x 2 images per thread; de-dup fp32 weights; f32x2 math;
//    base-2 no-max softmax; X stashed to smem in dead phases.
// CTA: 256 threads = 8 warps = 8 slots = 16 images. grid = B/16.

namespace {
constexpr int NB  = 4;
constexpr int TT  = 50;
constexpr int NTH = 256;
constexpr int WPC = 8;     // warps (slots) per CTA
constexpr int IPC = 16;    // images per CTA
constexpr int ROW  = 18;   // u64 per kv token row (144B: k[0..7], pad, v[10..17])
constexpr int VOFF = 10;
constexpr int KV_U64 = WPC * TT * ROW;        // 7200
constexpr int ST_STR = 18;                    // stash stride (u64)
constexpr int ST_U64 = WPC * 25 * ST_STR;     // 3600

struct SW {  // de-duplicated fp32 weights
  float Wq[NB * 64], Wk[NB * 64], Wv[NB * 64], projW[NB * 64];
  float W1[NB * 256], W2t[NB * 256];
  float ln1g[NB * 8], ln1b[NB * 8], ln2g[NB * 8], ln2b[NB * 8];
  float projb[NB * 8], b1[NB * 32], b2[NB * 8];
  float linW[128];
  float cls[8];
  float pos[TT * 8];
  float mlpW[80], mlpb[12];
};
}  // namespace

typedef unsigned long long u64;

__device__ __forceinline__ u64 pk2(float a, float b) {
  u64 r;
  asm("mov.b64 %0, {%1, %2};" : "=l"(r)
      : "r"(__float_as_uint(a)), "r"(__float_as_uint(b)));
  return r;
}
__device__ __forceinline__ u64 pk1(float a) {
  u64 r;
  asm("mov.b64 %0, {%1, %1};" : "=l"(r) : "r"(__float_as_uint(a)));
  return r;
}
__device__ __forceinline__ void upk2(u64 v, float& a, float& b) {
  unsigned int x, y;
  asm("mov.b64 {%0, %1}, %2;" : "=r"(x), "=r"(y) : "l"(v));
  a = __uint_as_float(x); b = __uint_as_float(y);
}
__device__ __forceinline__ u64 fma2(u64 a, u64 b, u64 c) {
  u64 d;
  asm("fma.rn.f32x2 %0, %1, %2, %3;" : "=l"(d) : "l"(a), "l"(b), "l"(c));
  return d;
}
__device__ __forceinline__ u64 add2(u64 a, u64 b) {
  u64 d;
  asm("add.rn.f32x2 %0, %1, %2;" : "=l"(d) : "l"(a), "l"(b));
  return d;
}
__device__ __forceinline__ u64 mul2(u64 a, u64 b) {
  u64 d;
  asm("mul.rn.f32x2 %0, %1, %2;" : "=l"(d) : "l"(a), "l"(b));
  return d;
}
__device__ __forceinline__ float ex2f(float x) {
  float r;
  asm("ex2.approx.ftz.f32 %0, %1;" : "=f"(r) : "f"(x));
  return r;
}

// load 8-float row (2x LDS.128 broadcast) and pack to {w,w} dup pairs
__device__ __forceinline__ void ldrow8pk(const float* __restrict__ w, u64 wd[8]) {
  float4 w0 = *reinterpret_cast<const float4*>(w);
  float4 w1 = *reinterpret_cast<const float4*>(w + 4);
  wd[0] = pk1(w0.x); wd[1] = pk1(w0.y); wd[2] = pk1(w0.z); wd[3] = pk1(w0.w);
  wd[4] = pk1(w1.x); wd[5] = pk1(w1.y); wd[6] = pk1(w1.z); wd[7] = pk1(w1.w);
}

__device__ __forceinline__ u64 dot8r(const u64 wd[8], const u64 h[8]) {
  u64 s0 = mul2(h[0], wd[0]);
  u64 s1 = mul2(h[1], wd[1]);
  s0 = fma2(h[2], wd[2], s0); s1 = fma2(h[3], wd[3], s1);
  s0 = fma2(h[4], wd[4], s0); s1 = fma2(h[5], wd[5], s1);
  s0 = fma2(h[6], wd[6], s0); s1 = fma2(h[7], wd[7], s1);
  return add2(s0, s1);
}

__device__ __forceinline__ void lnp(const u64 x[8], const u64 g[8],
                                    const u64 b[8], u64 h[8]) {
  u64 s = add2(add2(add2(x[0], x[1]), add2(x[2], x[3])),
               add2(add2(x[4], x[5]), add2(x[6], x[7])));
  float sA, sB;
  upk2(s, sA, sB);
  u64 mu = pk2(sA * 0.125f, sB * 0.125f);
  const u64 N1 = pk1(-1.f);
  u64 c[8];
#pragma unroll
  for (int d = 0; d < 8; d++) c[d] = fma2(mu, N1, x[d]);
  u64 v0 = mul2(c[0], c[0]);
  u64 v1 = mul2(c[1], c[1]);
  v0 = fma2(c[2], c[2], v0); v1 = fma2(c[3], c[3], v1);
  v0 = fma2(c[4], c[4], v0); v1 = fma2(c[5], c[5], v1);
  v0 = fma2(c[6], c[6], v0); v1 = fma2(c[7], c[7], v1);
  float vA, vB;
  upk2(add2(v0, v1), vA, vB);
  u64 rs = pk2(rsqrtf(fmaf(vA, 0.125f, 1e-5f)),
               rsqrtf(fmaf(vB, 0.125f, 1e-5f)));
#pragma unroll
  for (int d = 0; d < 8; d++) h[d] = fma2(mul2(c[d], rs), g[d], b[d]);
}

__global__ void __launch_bounds__(NTH, 2) vit_kernel(
    const float* __restrict__ images, const float* __restrict__ cls_g,
    const float* __restrict__ linW_g, const float* __restrict__ ln1g_g,
    const float* __restrict__ ln1b_g, const float* __restrict__ Wq_g,
    const float* __restrict__ Wk_g, const float* __restrict__ Wv_g,
    const float* __restrict__ projW_g, const float* __restrict__ projb_g,
    const float* __restrict__ ln2g_g, const float* __restrict__ ln2b_g,
    const float* __restrict__ W1_g, const float* __restrict__ b1_g,
    const float* __restrict__ W2_g, const float* __restrict__ b2_g,
    const float* __restrict__ mlpW_g, const float* __restrict__ mlpb_g,
    float* __restrict__ out, int B) {
  extern __shared__ __align__(16) char dsm[];
  u64* skv   = reinterpret_cast<u64*>(dsm);
  u64* stash = skv + KV_U64;
  SW* sw = reinterpret_cast<SW*>(reinterpret_cast<char*>(stash + ST_U64));

  const int tid = threadIdx.x;

  // ---- stage weights (plain fp32, no duplication) ----
  {
    auto cp = [&](float* d, const float* s, int n) {
      for (int i = tid; i < n; i += NTH) d[i] = s[i];
    };
    cp(sw->Wq, Wq_g, NB * 64);   cp(sw->Wk, Wk_g, NB * 64);
    cp(sw->Wv, Wv_g, NB * 64);   cp(sw->projW, projW_g, NB * 64);
    cp(sw->W1, W1_g, NB * 256);
    cp(sw->ln1g, ln1g_g, NB * 8); cp(sw->ln1b, ln1b_g, NB * 8);
    cp(sw->ln2g, ln2g_g, NB * 8); cp(sw->ln2b, ln2b_g, NB * 8);
    cp(sw->projb, projb_g, NB * 8);
    cp(sw->b1, b1_g, NB * 32);    cp(sw->b2, b2_g, NB * 8);
    cp(sw->linW, linW_g, 128);
    cp(sw->cls, cls_g, 8);
    cp(sw->mlpW, mlpW_g, 80);
    for (int i = tid; i < 10; i += NTH) sw->mlpb[i] = mlpb_g[i];
    // W2 [blk][8][32] -> transposed [blk][32][8]
    for (int i = tid; i < NB * 256; i += NTH) {
      int blk = i >> 8, rem = i & 255, f = rem >> 3, d = rem & 7;
      sw->W2t[blk * 256 + rem] = W2_g[blk * 256 + d * 32 + f];
    }
    if (tid < TT) {  // sinusoidal table: freqs {1, .1, .01, .001}
      float tf = (float)tid;
      float* p = sw->pos + tid * 8;
      p[0] = sinf(tf);          p[1] = cosf(tf);
      p[2] = sinf(tf * 0.1f);   p[3] = cosf(tf * 0.1f);
      p[4] = sinf(tf * 0.01f);  p[5] = cosf(tf * 0.01f);
      p[6] = sinf(tf * 0.001f); p[7] = cosf(tf * 0.001f);
    }
  }
  __syncthreads();

  const int warp = tid >> 5;
  const int lane = tid & 31;
  const bool act = (lane < 25);
  const int t0 = lane;
  const int t1 = lane + 25;
  const int gb0 = (blockIdx.x * WPC + warp) * 2;
  const int gb1 = gb0 + 1;

  u64* kvb = skv + warp * (TT * ROW);
  u64* xs  = stash + (warp * 25 + lane) * ST_STR;  // 16 u64 per thread

  u64 X0[8], X1[8];  // token t0, t1 activations ({imgA,imgB} pairs)

  // ---- patch embed + positional (cold path, scalar fp32) ----
  if (act) {
    auto embed_tok = [&](int t, u64 xr[8]) {
      if (t == 0) {
#pragma unroll
        for (int d = 0; d < 8; d++) {
          float v = sw->cls[d] + sw->pos[d];
          xr[d] = pk1(v);
        }
        return;
      }
      int p = t - 1, r = p / 7, c = p % 7;
      float eo[2][8];
#pragma unroll
      for (int img = 0; img < 2; img++) {
        int gb = gb0 + img;
        float px[16];
        if (gb < B) {
          const float* ip = images + (size_t)gb * 784 + (r * 4) * 28 + c * 4;
#pragma unroll
          for (int i = 0; i < 4; i++) {
            float4 v4 = *reinterpret_cast<const float4*>(ip + i * 28);
            px[4 * i] = v4.x; px[4 * i + 1] = v4.y;
            px[4 * i + 2] = v4.z; px[4 * i + 3] = v4.w;
          }
        } else {
#pragma unroll
          for (int j = 0; j < 16; j++) px[j] = 0.f;
        }
#pragma unroll
        for (int d = 0; d < 8; d++) {
          const float* w = sw->linW + d * 16;
          float s = 0.f;
#pragma unroll
          for (int j = 0; j < 16; j++) s = fmaf(px[j], w[j], s);
          eo[img][d] = s + sw->pos[t * 8 + d];
        }
      }
#pragma unroll
      for (int d = 0; d < 8; d++) xr[d] = pk2(eo[0][d], eo[1][d]);
    };
    embed_tok(t0, X0);
    embed_tok(t1, X1);
  }

  // scale * log2(e): softmax in base 2
  const float SCL2E = 0.35355339059327373f * 1.4426950408889634f;

#pragma unroll 1
  for (int blk = 0; blk < NB; blk++) {
    u64 Q0[8], Q1[8];
    if (act) {
      // LN1 (packed gamma/beta shared across both tokens)
      u64 gp[8], bp[8], H0[8], H1[8];
      ldrow8pk(sw->ln1g + blk * 8, gp);
      ldrow8pk(sw->ln1b + blk * 8, bp);
      lnp(X0, gp, bp, H0);
      lnp(X1, gp, bp, H1);
      // stash X (dead until proj residual)
      {
        ulonglong2* s2 = reinterpret_cast<ulonglong2*>(xs);
#pragma unroll
        for (int i = 0; i < 4; i++)
          s2[i] = make_ulonglong2(X0[2 * i], X0[2 * i + 1]);
#pragma unroll
        for (int i = 0; i < 4; i++)
          s2[4 + i] = make_ulonglong2(X1[2 * i], X1[2 * i + 1]);
      }
      const u64 SC2 = pk1(SCL2E);
      u64 wd[8];
      const float* wq = sw->Wq + blk * 64;
#pragma unroll
      for (int e = 0; e < 8; e++) {
        ldrow8pk(wq + e * 8, wd);
        Q0[e] = mul2(dot8r(wd, H0), SC2);
        Q1[e] = mul2(dot8r(wd, H1), SC2);
      }
      const float* wk = sw->Wk + blk * 64;
      u64* kr0 = kvb + t0 * ROW;
      u64* kr1 = kvb + t1 * ROW;
#pragma unroll
      for (int e = 0; e < 8; e++) {
        ldrow8pk(wk + e * 8, wd);
        kr0[e] = dot8r(wd, H0);
        kr1[e] = dot8r(wd, H1);
      }
      const float* wv = sw->Wv + blk * 64;
#pragma unroll
      for (int e = 0; e < 8; e++) {
        ldrow8pk(wv + e * 8, wd);
        kr0[VOFF + e] = dot8r(wd, H0);
        kr1[VOFF + e] = dot8r(wd, H1);
      }
    }
    __syncthreads();

    u64 O0[8], O1[8];
    if (act) {
      // base-2 no-max softmax, TWO sequential per-head passes.
      // Each pass: 4 LDS.128 per u (that head's K half + V half); live set
      // per pass = 8 Q-halves + 8 acc + 2 sums (vs 16 Q + 16 acc fused).
#pragma unroll 1
      for (int h = 0; h < 2; h++) {
        const u64 q00 = Q0[4 * h + 0], q01 = Q0[4 * h + 1];
        const u64 q02 = Q0[4 * h + 2], q03 = Q0[4 * h + 3];
        const u64 q10 = Q1[4 * h + 0], q11 = Q1[4 * h + 1];
        const u64 q12 = Q1[4 * h + 2], q13 = Q1[4 * h + 3];
        const u64* kh = kvb + 4 * h;
        const u64* vh = kvb + VOFF + 4 * h;
        u64 l0 = 0, l1 = 0;
        u64 a00 = 0, a01 = 0, a02 = 0, a03 = 0;
        u64 a10 = 0, a11 = 0, a12 = 0, a13 = 0;
#pragma unroll 2
        for (int u = 0; u < TT; u++) {
          const ulonglong2* kp =
              reinterpret_cast<const ulonglong2*>(kh + u * ROW);
          ulonglong2 k0 = kp[0], k1 = kp[1];
          const ulonglong2* vp =
              reinterpret_cast<const ulonglong2*>(vh + u * ROW);
          ulonglong2 v0 = vp[0], v1 = vp[1];
          u64 s0 = fma2(q00, k0.x,
                   fma2(q01, k0.y, fma2(q02, k1.x, mul2(q03, k1.y))));
          u64 s1 = fma2(q10, k0.x,
                   fma2(q11, k0.y, fma2(q12, k1.x, mul2(q13, k1.y))));
          float xa, xb;
          upk2(s0, xa, xb);
          u64 p0 = pk2(ex2f(xa), ex2f(xb));
          upk2(s1, xa, xb);
          u64 p1 = pk2(ex2f(xa), ex2f(xb));
          l0 = add2(l0, p0);
          l1 = add2(l1, p1);
          a00 = fma2(p0, v0.x, a00); a01 = fma2(p0, v0.y, a01);
          a02 = fma2(p0, v1.x, a02); a03 = fma2(p0, v1.y, a03);
          a10 = fma2(p1, v0.x, a10); a11 = fma2(p1, v0.y, a11);
          a12 = fma2(p1, v1.x, a12); a13 = fma2(p1, v1.y, a13);
        }
        float lA, lB;
        upk2(l0, lA, lB);
        u64 i0 = pk2(1.f / lA, 1.f / lB);
        upk2(l1, lA, lB);
        u64 i1 = pk2(1.f / lA, 1.f / lB);
        O0[4 * h + 0] = mul2(a00, i0); O0[4 * h + 1] = mul2(a01, i0);
        O0[4 * h + 2] = mul2(a02, i0); O0[4 * h + 3] = mul2(a03, i0);
        O1[4 * h + 0] = mul2(a10, i1); O1[4 * h + 1] = mul2(a11, i1);
        O1[4 * h + 2] = mul2(a12, i1); O1[4 * h + 3] = mul2(a13, i1);
      }
    }
    __syncthreads();  // kv consumed; next block may overwrite

    if (act) {
      // reload X, proj + residual
      {
        const ulonglong2* s2 = reinterpret_cast<const ulonglong2*>(xs);
#pragma unroll
        for (int i = 0; i < 4; i++) {
          ulonglong2 v = s2[i];
          X0[2 * i] = v.x; X0[2 * i + 1] = v.y;
        }
#pragma unroll
        for (int i = 0; i < 4; i++) {
          ulonglong2 v = s2[4 + i];
          X1[2 * i] = v.x; X1[2 * i + 1] = v.y;
        }
      }
      u64 wd[8], pbp[8];
      ldrow8pk(sw->projb + blk * 8, pbp);
      const float* pw = sw->projW + blk * 64;
#pragma unroll
      for (int e = 0; e < 8; e++) {
        ldrow8pk(pw + e * 8, wd);
        X0[e] = add2(X0[e], add2(dot8r(wd, O0), pbp[e]));
        X1[e] = add2(X1[e], add2(dot8r(wd, O1), pbp[e]));
      }

      // LN2
      u64 gp[8], bp[8], H0[8], H1[8];
      ldrow8pk(sw->ln2g + blk * 8, gp);
      ldrow8pk(sw->ln2b + blk * 8, bp);
      lnp(X0, gp, bp, H0);
      lnp(X1, gp, bp, H1);
      // stash X again (dead during MLP)
      {
        ulonglong2* s2 = reinterpret_cast<ulonglong2*>(xs);
#pragma unroll
        for (int i = 0; i < 4; i++)
          s2[i] = make_ulonglong2(X0[2 * i], X0[2 * i + 1]);
#pragma unroll
        for (int i = 0; i < 4; i++)
          s2[4 + i] = make_ulonglong2(X1[2 * i], X1[2 * i + 1]);
      }

      // MLP 8 -> 32 (relu) -> 8
      const float* w1 = sw->W1 + blk * 256;
      const float* b1 = sw->b1 + blk * 32;
      const float* w2 = sw->W2t + blk * 256;
      u64 acc0[8], acc1[8];
#pragma unroll
      for (int d = 0; d < 8; d++) { acc0[d] = 0; acc1[d] = 0; }
#pragma unroll 4
      for (int f = 0; f < 32; f++) {
        u64 wd2[8];
        ldrow8pk(w1 + f * 8, wd2);
        u64 bf = pk1(b1[f]);
        u64 f0 = add2(dot8r(wd2, H0), bf);
        u64 f1 = add2(dot8r(wd2, H1), bf);
        float fa, fb;
        upk2(f0, fa, fb);
        f0 = pk2(fmaxf(fa, 0.f), fmaxf(fb, 0.f));
        upk2(f1, fa, fb);
        f1 = pk2(fmaxf(fa, 0.f), fmaxf(fb, 0.f));
        ldrow8pk(w2 + f * 8, wd2);
#pragma unroll
        for (int d = 0; d < 8; d++) {
          acc0[d] = fma2(f0, wd2[d], acc0[d]);
          acc1[d] = fma2(f1, wd2[d], acc1[d]);
        }
      }
      // reload X, final residual
      u64 b2p[8];
      ldrow8pk(sw->b2 + blk * 8, b2p);
      {
        const ulonglong2* s2 = reinterpret_cast<const ulonglong2*>(xs);
#pragma unroll
        for (int i = 0; i < 4; i++) {
          ulonglong2 v = s2[i];
          X0[2 * i] = v.x; X0[2 * i + 1] = v.y;
        }
#pragma unroll
        for (int i = 0; i < 4; i++) {
          ulonglong2 v = s2[4 + i];
          X1[2 * i] = v.x; X1[2 * i + 1] = v.y;
        }
      }
#pragma unroll
      for (int d = 0; d < 8; d++) {
        X0[d] = add2(X0[d], add2(acc0[d], b2p[d]));
        X1[d] = add2(X1[d], add2(acc1[d], b2p[d]));
      }
    }
  }

  // classification head on token 0 (lane 0's t0): softmax(x0 @ mlpW^T + mlpb)
  if (act && lane == 0) {
    float xA[8], xB[8];
#pragma unroll
    for (int d = 0; d < 8; d++) upk2(X0[d], xA[d], xB[d]);
    auto head = [&](const float x[8], int gb) {
      if (gb >= B) return;
      float z[10];
      float zm = -1e30f;
#pragma unroll
      for (int c = 0; c < 10; c++) {
        const float* w = sw->mlpW + c * 8;
        float s = sw->mlpb[c];
#pragma unroll
        for (int j = 0; j < 8; j++) s = fmaf(x[j], w[j], s);
        z[c] = s;
        zm = fmaxf(zm, s);
      }
      float ssum = 0.f;
#pragma unroll
      for (int c = 0; c < 10; c++) { z[c] = __expf(z[c] - zm); ssum += z[c]; }
      float inv = 1.f / ssum;
#pragma unroll
      for (int c = 0; c < 10; c++) out[gb * 10 + c] = z[c] * inv;
    };
    head(xA, gb0);
    head(xB, gb1);
  }
}

extern "C" void kernel_launch(void* const* d_in, const int* in_sizes, int n_in,
                              void* d_out, int out_size) {
  const float* images = (const float*)d_in[0];
  const float* cls    = (const float*)d_in[1];
  const float* linW   = (const float*)d_in[2];
  const float* ln1g   = (const float*)d_in[3];
  const float* ln1b   = (const float*)d_in[4];
  const float* Wq     = (const float*)d_in[5];
  const float* Wk     = (const float*)d_in[6];
  const float* Wv     = (const float*)d_in[7];
  const float* projW  = (const float*)d_in[8];
  const float* projb  = (const float*)d_in[9];
  const float* ln2g   = (const float*)d_in[10];
  const float* ln2b   = (const float*)d_in[11];
  const float* W1     = (const float*)d_in[12];
  const float* b1     = (const float*)d_in[13];
  const float* W2     = (const float*)d_in[14];
  const float* b2     = (const float*)d_in[15];
  const float* mlpW   = (const float*)d_in[16];
  const float* mlpb   = (const float*)d_in[17];

  int B = in_sizes[0] / 784;
  int smem = (KV_U64 + ST_U64) * 8 + (int)sizeof(SW);
  cudaFuncSetAttribute(vit_kernel, cudaFuncAttributeMaxDynamicSharedMemorySize,
                       smem);
  dim3 grid((B + IPC - 1) / IPC);
  vit_kernel<<<grid, NTH, smem>>>(images, cls, linW, ln1g, ln1b, Wq, Wk, Wv,
                                  projW, projb, ln2g, ln2b, W1, b1, W2, b2,
                                  mlpW, mlpb, (float*)d_out, B);
}

// round 10
// speedup vs baseline: 1.6283x; 1.0379x over previous
#include <cuda_runtime.h>

// Tiny-ViT fused forward, round 8: R7 + warp-decoupled execution.
//  - K/V and X-stash are warp-private since R5 -> ALL in-loop __syncthreads()
//    replaced by __syncwarp(): warps never wait on each other, one warp's
//    attention overlaps another's QKV/MLP (issue-starvation fix).
//  - head-split attention, 2 tokens x 2 images per thread, de-dup fp32
//    weights, f32x2 math, base-2 no-max softmax.
// CTA: 256 threads = 8 warps = 8 slots = 16 images. grid = B/16.

namespace {
constexpr int NB  = 4;
constexpr int TT  = 50;
constexpr int NTH = 256;
constexpr int WPC = 8;     // warps (slots) per CTA
constexpr int IPC = 16;    // images per CTA
constexpr int ROW  = 18;   // u64 per kv token row (144B: k[0..7], pad, v[10..17])
constexpr int VOFF = 10;
constexpr int KV_U64 = WPC * TT * ROW;        // 7200
constexpr int ST_STR = 18;                    // stash stride (u64)
constexpr int ST_U64 = WPC * 25 * ST_STR;     // 3600

struct SW {  // de-duplicated fp32 weights
  float Wq[NB * 64], Wk[NB * 64], Wv[NB * 64], projW[NB * 64];
  float W1[NB * 256], W2t[NB * 256];
  float ln1g[NB * 8], ln1b[NB * 8], ln2g[NB * 8], ln2b[NB * 8];
  float projb[NB * 8], b1[NB * 32], b2[NB * 8];
  float linW[128];
  float cls[8];
  float pos[TT * 8];
  float mlpW[80], mlpb[12];
};
}  // namespace

typedef unsigned long long u64;

__device__ __forceinline__ u64 pk2(float a, float b) {
  u64 r;
  asm("mov.b64 %0, {%1, %2};" : "=l"(r)
      : "r"(__float_as_uint(a)), "r"(__float_as_uint(b)));
  return r;
}
__device__ __forceinline__ u64 pk1(float a) {
  u64 r;
  asm("mov.b64 %0, {%1, %1};" : "=l"(r) : "r"(__float_as_uint(a)));
  return r;
}
__device__ __forceinline__ void upk2(u64 v, float& a, float& b) {
  unsigned int x, y;
  asm("mov.b64 {%0, %1}, %2;" : "=r"(x), "=r"(y) : "l"(v));
  a = __uint_as_float(x); b = __uint_as_float(y);
}
__device__ __forceinline__ u64 fma2(u64 a, u64 b, u64 c) {
  u64 d;
  asm("fma.rn.f32x2 %0, %1, %2, %3;" : "=l"(d) : "l"(a), "l"(b), "l"(c));
  return d;
}
__device__ __forceinline__ u64 add2(u64 a, u64 b) {
  u64 d;
  asm("add.rn.f32x2 %0, %1, %2;" : "=l"(d) : "l"(a), "l"(b));
  return d;
}
__device__ __forceinline__ u64 mul2(u64 a, u64 b) {
  u64 d;
  asm("mul.rn.f32x2 %0, %1, %2;" : "=l"(d) : "l"(a), "l"(b));
  return d;
}
__device__ __forceinline__ float ex2f(float x) {
  float r;
  asm("ex2.approx.ftz.f32 %0, %1;" : "=f"(r) : "f"(x));
  return r;
}

// load 8-float row (2x LDS.128 broadcast) and pack to {w,w} dup pairs
__device__ __forceinline__ void ldrow8pk(const float* __restrict__ w, u64 wd[8]) {
  float4 w0 = *reinterpret_cast<const float4*>(w);
  float4 w1 = *reinterpret_cast<const float4*>(w + 4);
  wd[0] = pk1(w0.x); wd[1] = pk1(w0.y); wd[2] = pk1(w0.z); wd[3] = pk1(w0.w);
  wd[4] = pk1(w1.x); wd[5] = pk1(w1.y); wd[6] = pk1(w1.z); wd[7] = pk1(w1.w);
}

__device__ __forceinline__ u64 dot8r(const u64 wd[8], const u64 h[8]) {
  u64 s0 = mul2(h[0], wd[0]);
  u64 s1 = mul2(h[1], wd[1]);
  s0 = fma2(h[2], wd[2], s0); s1 = fma2(h[3], wd[3], s1);
  s0 = fma2(h[4], wd[4], s0); s1 = fma2(h[5], wd[5], s1);
  s0 = fma2(h[6], wd[6], s0); s1 = fma2(h[7], wd[7], s1);
  return add2(s0, s1);
}

__device__ __forceinline__ void lnp(const u64 x[8], const u64 g[8],
                                    const u64 b[8], u64 h[8]) {
  u64 s = add2(add2(add2(x[0], x[1]), add2(x[2], x[3])),
               add2(add2(x[4], x[5]), add2(x[6], x[7])));
  float sA, sB;
  upk2(s, sA, sB);
  u64 mu = pk2(sA * 0.125f, sB * 0.125f);
  const u64 N1 = pk1(-1.f);
  u64 c[8];
#pragma unroll
  for (int d = 0; d < 8; d++) c[d] = fma2(mu, N1, x[d]);
  u64 v0 = mul2(c[0], c[0]);
  u64 v1 = mul2(c[1], c[1]);
  v0 = fma2(c[2], c[2], v0); v1 = fma2(c[3], c[3], v1);
  v0 = fma2(c[4], c[4], v0); v1 = fma2(c[5], c[5], v1);
  v0 = fma2(c[6], c[6], v0); v1 = fma2(c[7], c[7], v1);
  float vA, vB;
  upk2(add2(v0, v1), vA, vB);
  u64 rs = pk2(rsqrtf(fmaf(vA, 0.125f, 1e-5f)),
               rsqrtf(fmaf(vB, 0.125f, 1e-5f)));
#pragma unroll
  for (int d = 0; d < 8; d++) h[d] = fma2(mul2(c[d], rs), g[d], b[d]);
}

__global__ void __launch_bounds__(NTH, 2) vit_kernel(
    const float* __restrict__ images, const float* __restrict__ cls_g,
    const float* __restrict__ linW_g, const float* __restrict__ ln1g_g,
    const float* __restrict__ ln1b_g, const float* __restrict__ Wq_g,
    const float* __restrict__ Wk_g, const float* __restrict__ Wv_g,
    const float* __restrict__ projW_g, const float* __restrict__ projb_g,
    const float* __restrict__ ln2g_g, const float* __restrict__ ln2b_g,
    const float* __restrict__ W1_g, const float* __restrict__ b1_g,
    const float* __restrict__ W2_g, const float* __restrict__ b2_g,
    const float* __restrict__ mlpW_g, const float* __restrict__ mlpb_g,
    float* __restrict__ out, int B) {
  extern __shared__ __align__(16) char dsm[];
  u64* skv   = reinterpret_cast<u64*>(dsm);
  u64* stash = skv + KV_U64;
  SW* sw = reinterpret_cast<SW*>(reinterpret_cast<char*>(stash + ST_U64));

  const int tid = threadIdx.x;

  // ---- stage weights (plain fp32, no duplication) ----
  {
    auto cp = [&](float* d, const float* s, int n) {
      for (int i = tid; i < n; i += NTH) d[i] = s[i];
    };
    cp(sw->Wq, Wq_g, NB * 64);   cp(sw->Wk, Wk_g, NB * 64);
    cp(sw->Wv, Wv_g, NB * 64);   cp(sw->projW, projW_g, NB * 64);
    cp(sw->W1, W1_g, NB * 256);
    cp(sw->ln1g, ln1g_g, NB * 8); cp(sw->ln1b, ln1b_g, NB * 8);
    cp(sw->ln2g, ln2g_g, NB * 8); cp(sw->ln2b, ln2b_g, NB * 8);
    cp(sw->projb, projb_g, NB * 8);
    cp(sw->b1, b1_g, NB * 32);    cp(sw->b2, b2_g, NB * 8);
    cp(sw->linW, linW_g, 128);
    cp(sw->cls, cls_g, 8);
    cp(sw->mlpW, mlpW_g, 80);
    for (int i = tid; i < 10; i += NTH) sw->mlpb[i] = mlpb_g[i];
    // W2 [blk][8][32] -> transposed [blk][32][8]
    for (int i = tid; i < NB * 256; i += NTH) {
      int blk = i >> 8, rem = i & 255, f = rem >> 3, d = rem & 7;
      sw->W2t[blk * 256 + rem] = W2_g[blk * 256 + d * 32 + f];
    }
    if (tid < TT) {  // sinusoidal table: freqs {1, .1, .01, .001}
      float tf = (float)tid;
      float* p = sw->pos + tid * 8;
      p[0] = sinf(tf);          p[1] = cosf(tf);
      p[2] = sinf(tf * 0.1f);   p[3] = cosf(tf * 0.1f);
      p[4] = sinf(tf * 0.01f);  p[5] = cosf(tf * 0.01f);
      p[6] = sinf(tf * 0.001f); p[7] = cosf(tf * 0.001f);
    }
  }
  __syncthreads();  // real CTA-wide dependency: weights staged cooperatively

  const int warp = tid >> 5;
  const int lane = tid & 31;
  const bool act = (lane < 25);
  const int t0 = lane;
  const int t1 = lane + 25;
  const int gb0 = (blockIdx.x * WPC + warp) * 2;
  const int gb1 = gb0 + 1;

  u64* kvb = skv + warp * (TT * ROW);
  u64* xs  = stash + (warp * 25 + lane) * ST_STR;  // 16 u64 per thread

  u64 X0[8], X1[8];  // token t0, t1 activations ({imgA,imgB} pairs)

  // ---- patch embed + positional (cold path, scalar fp32) ----
  if (act) {
    auto embed_tok = [&](int t, u64 xr[8]) {
      if (t == 0) {
#pragma unroll
        for (int d = 0; d < 8; d++) {
          float v = sw->cls[d] + sw->pos[d];
          xr[d] = pk1(v);
        }
        return;
      }
      int p = t - 1, r = p / 7, c = p % 7;
      float eo[2][8];
#pragma unroll
      for (int img = 0; img < 2; img++) {
        int gb = gb0 + img;
        float px[16];
        if (gb < B) {
          const float* ip = images + (size_t)gb * 784 + (r * 4) * 28 + c * 4;
#pragma unroll
          for (int i = 0; i < 4; i++) {
            float4 v4 = *reinterpret_cast<const float4*>(ip + i * 28);
            px[4 * i] = v4.x; px[4 * i + 1] = v4.y;
            px[4 * i + 2] = v4.z; px[4 * i + 3] = v4.w;
          }
        } else {
#pragma unroll
          for (int j = 0; j < 16; j++) px[j] = 0.f;
        }
#pragma unroll
        for (int d = 0; d < 8; d++) {
          const float* w = sw->linW + d * 16;
          float s = 0.f;
#pragma unroll
          for (int j = 0; j < 16; j++) s = fmaf(px[j], w[j], s);
          eo[img][d] = s + sw->pos[t * 8 + d];
        }
      }
#pragma unroll
      for (int d = 0; d < 8; d++) xr[d] = pk2(eo[0][d], eo[1][d]);
    };
    embed_tok(t0, X0);
    embed_tok(t1, X1);
  }

  // scale * log2(e): softmax in base 2
  const float SCL2E = 0.35355339059327373f * 1.4426950408889634f;

#pragma unroll 1
  for (int blk = 0; blk < NB; blk++) {
    u64 Q0[8], Q1[8];
    if (act) {
      // LN1 (packed gamma/beta shared across both tokens)
      u64 gp[8], bp[8], H0[8], H1[8];
      ldrow8pk(sw->ln1g + blk * 8, gp);
      ldrow8pk(sw->ln1b + blk * 8, bp);
      lnp(X0, gp, bp, H0);
      lnp(X1, gp, bp, H1);
      // stash X (dead until proj residual)
      {
        ulonglong2* s2 = reinterpret_cast<ulonglong2*>(xs);
#pragma unroll
        for (int i = 0; i < 4; i++)
          s2[i] = make_ulonglong2(X0[2 * i], X0[2 * i + 1]);
#pragma unroll
        for (int i = 0; i < 4; i++)
          s2[4 + i] = make_ulonglong2(X1[2 * i], X1[2 * i + 1]);
      }
      const u64 SC2 = pk1(SCL2E);
      u64 wd[8];
      const float* wq = sw->Wq + blk * 64;
#pragma unroll
      for (int e = 0; e < 8; e++) {
        ldrow8pk(wq + e * 8, wd);
        Q0[e] = mul2(dot8r(wd, H0), SC2);
        Q1[e] = mul2(dot8r(wd, H1), SC2);
      }
      const float* wk = sw->Wk + blk * 64;
      u64* kr0 = kvb + t0 * ROW;
      u64* kr1 = kvb + t1 * ROW;
#pragma unroll
      for (int e = 0; e < 8; e++) {
        ldrow8pk(wk + e * 8, wd);
        kr0[e] = dot8r(wd, H0);
        kr1[e] = dot8r(wd, H1);
      }
      const float* wv = sw->Wv + blk * 64;
#pragma unroll
      for (int e = 0; e < 8; e++) {
        ldrow8pk(wv + e * 8, wd);
        kr0[VOFF + e] = dot8r(wd, H0);
        kr1[VOFF + e] = dot8r(wd, H1);
      }
    }
    __syncwarp();  // K/V is warp-private: warp-level sync suffices

    u64 O0[8], O1[8];
    if (act) {
      // base-2 no-max softmax, TWO sequential per-head passes.
#pragma unroll 1
      for (int h = 0; h < 2; h++) {
        const u64 q00 = Q0[4 * h + 0], q01 = Q0[4 * h + 1];
        const u64 q02 = Q0[4 * h + 2], q03 = Q0[4 * h + 3];
        const u64 q10 = Q1[4 * h + 0], q11 = Q1[4 * h + 1];
        const u64 q12 = Q1[4 * h + 2], q13 = Q1[4 * h + 3];
        const u64* kh = kvb + 4 * h;
        const u64* vh = kvb + VOFF + 4 * h;
        u64 l0 = 0, l1 = 0;
        u64 a00 = 0, a01 = 0, a02 = 0, a03 = 0;
        u64 a10 = 0, a11 = 0, a12 = 0, a13 = 0;
#pragma unroll 2
        for (int u = 0; u < TT; u++) {
          const ulonglong2* kp =
              reinterpret_cast<const ulonglong2*>(kh + u * ROW);
          ulonglong2 k0 = kp[0], k1 = kp[1];
          const ulonglong2* vp =
              reinterpret_cast<const ulonglong2*>(vh + u * ROW);
          ulonglong2 v0 = vp[0], v1 = vp[1];
          u64 s0 = fma2(q00, k0.x,
                   fma2(q01, k0.y, fma2(q02, k1.x, mul2(q03, k1.y))));
          u64 s1 = fma2(q10, k0.x,
                   fma2(q11, k0.y, fma2(q12, k1.x, mul2(q13, k1.y))));
          float xa, xb;
          upk2(s0, xa, xb);
          u64 p0 = pk2(ex2f(xa), ex2f(xb));
          upk2(s1, xa, xb);
          u64 p1 = pk2(ex2f(xa), ex2f(xb));
          l0 = add2(l0, p0);
          l1 = add2(l1, p1);
          a00 = fma2(p0, v0.x, a00); a01 = fma2(p0, v0.y, a01);
          a02 = fma2(p0, v1.x, a02); a03 = fma2(p0, v1.y, a03);
          a10 = fma2(p1, v0.x, a10); a11 = fma2(p1, v0.y, a11);
          a12 = fma2(p1, v1.x, a12); a13 = fma2(p1, v1.y, a13);
        }
        float lA, lB;
        upk2(l0, lA, lB);
        u64 i0 = pk2(1.f / lA, 1.f / lB);
        upk2(l1, lA, lB);
        u64 i1 = pk2(1.f / lA, 1.f / lB);
        O0[4 * h + 0] = mul2(a00, i0); O0[4 * h + 1] = mul2(a01, i0);
        O0[4 * h + 2] = mul2(a02, i0); O0[4 * h + 3] = mul2(a03, i0);
        O1[4 * h + 0] = mul2(a10, i1); O1[4 * h + 1] = mul2(a11, i1);
        O1[4 * h + 2] = mul2(a12, i1); O1[4 * h + 3] = mul2(a13, i1);
      }
    }
    __syncwarp();  // kv consumed; this warp may overwrite next block

    if (act) {
      // reload X, proj + residual
      {
        const ulonglong2* s2 = reinterpret_cast<const ulonglong2*>(xs);
#pragma unroll
        for (int i = 0; i < 4; i++) {
          ulonglong2 v = s2[i];
          X0[2 * i] = v.x; X0[2 * i + 1] = v.y;
        }
#pragma unroll
        for (int i = 0; i < 4; i++) {
          ulonglong2 v = s2[4 + i];
          X1[2 * i] = v.x; X1[2 * i + 1] = v.y;
        }
      }
      u64 wd[8], pbp[8];
      ldrow8pk(sw->projb + blk * 8, pbp);
      const float* pw = sw->projW + blk * 64;
#pragma unroll
      for (int e = 0; e < 8; e++) {
        ldrow8pk(pw + e * 8, wd);
        X0[e] = add2(X0[e], add2(dot8r(wd, O0), pbp[e]));
        X1[e] = add2(X1[e], add2(dot8r(wd, O1), pbp[e]));
      }

      // LN2
      u64 gp[8], bp[8], H0[8], H1[8];
      ldrow8pk(sw->ln2g + blk * 8, gp);
      ldrow8pk(sw->ln2b + blk * 8, bp);
      lnp(X0, gp, bp, H0);
      lnp(X1, gp, bp, H1);
      // stash X again (dead during MLP)
      {
        ulonglong2* s2 = reinterpret_cast<ulonglong2*>(xs);
#pragma unroll
        for (int i = 0; i < 4; i++)
          s2[i] = make_ulonglong2(X0[2 * i], X0[2 * i + 1]);
#pragma unroll
        for (int i = 0; i < 4; i++)
          s2[4 + i] = make_ulonglong2(X1[2 * i], X1[2 * i + 1]);
      }

      // MLP 8 -> 32 (relu) -> 8
      const float* w1 = sw->W1 + blk * 256;
      const float* b1 = sw->b1 + blk * 32;
      const float* w2 = sw->W2t + blk * 256;
      u64 acc0[8], acc1[8];
#pragma unroll
      for (int d = 0; d < 8; d++) { acc0[d] = 0; acc1[d] = 0; }
#pragma unroll 4
      for (int f = 0; f < 32; f++) {
        u64 wd2[8];
        ldrow8pk(w1 + f * 8, wd2);
        u64 bf = pk1(b1[f]);
        u64 f0 = add2(dot8r(wd2, H0), bf);
        u64 f1 = add2(dot8r(wd2, H1), bf);
        float fa, fb;
        upk2(f0, fa, fb);
        f0 = pk2(fmaxf(fa, 0.f), fmaxf(fb, 0.f));
        upk2(f1, fa, fb);
        f1 = pk2(fmaxf(fa, 0.f), fmaxf(fb, 0.f));
        ldrow8pk(w2 + f * 8, wd2);
#pragma unroll
        for (int d = 0; d < 8; d++) {
          acc0[d] = fma2(f0, wd2[d], acc0[d]);
          acc1[d] = fma2(f1, wd2[d], acc1[d]);
        }
      }
      // reload X, final residual
      u64 b2p[8];
      ldrow8pk(sw->b2 + blk * 8, b2p);
      {
        const ulonglong2* s2 = reinterpret_cast<const ulonglong2*>(xs);
#pragma unroll
        for (int i = 0; i < 4; i++) {
          ulonglong2 v = s2[i];
          X0[2 * i] = v.x; X0[2 * i + 1] = v.y;
        }
#pragma unroll
        for (int i = 0; i < 4; i++) {
          ulonglong2 v = s2[4 + i];
          X1[2 * i] = v.x; X1[2 * i + 1] = v.y;
        }
      }
#pragma unroll
      for (int d = 0; d < 8; d++) {
        X0[d] = add2(X0[d], add2(acc0[d], b2p[d]));
        X1[d] = add2(X1[d], add2(acc1[d], b2p[d]));
      }
    }
  }

  // classification head on token 0 (lane 0's t0): softmax(x0 @ mlpW^T + mlpb)
  if (act && lane == 0) {
    float xA[8], xB[8];
#pragma unroll
    for (int d = 0; d < 8; d++) upk2(X0[d], xA[d], xB[d]);
    auto head = [&](const float x[8], int gb) {
      if (gb >= B) return;
      float z[10];
      float zm = -1e30f;
#pragma unroll
      for (int c = 0; c < 10; c++) {
        const float* w = sw->mlpW + c * 8;
        float s = sw->mlpb[c];
#pragma unroll
        for (int j = 0; j < 8; j++) s = fmaf(x[j], w[j], s);
        z[c] = s;
        zm = fmaxf(zm, s);
      }
      float ssum = 0.f;
#pragma unroll
      for (int c = 0; c < 10; c++) { z[c] = __expf(z[c] - zm); ssum += z[c]; }
      float inv = 1.f / ssum;
#pragma unroll
      for (int c = 0; c < 10; c++) out[gb * 10 + c] = z[c] * inv;
    };
    head(xA, gb0);
    head(xB, gb1);
  }
}

extern "C" void kernel_launch(void* const* d_in, const int* in_sizes, int n_in,
                              void* d_out, int out_size) {
  const float* images = (const float*)d_in[0];
  const float* cls    = (const float*)d_in[1];
  const float* linW   = (const float*)d_in[2];
  const float* ln1g   = (const float*)d_in[3];
  const float* ln1b   = (const float*)d_in[4];
  const float* Wq     = (const float*)d_in[5];
  const float* Wk     = (const float*)d_in[6];
  const float* Wv     = (const float*)d_in[7];
  const float* projW  = (const float*)d_in[8];
  const float* projb  = (const float*)d_in[9];
  const float* ln2g   = (const float*)d_in[10];
  const float* ln2b   = (const float*)d_in[11];
  const float* W1     = (const float*)d_in[12];
  const float* b1     = (const float*)d_in[13];
  const float* W2     = (const float*)d_in[14];
  const float* b2     = (const float*)d_in[15];
  const float* mlpW   = (const float*)d_in[16];
  const float* mlpb   = (const float*)d_in[17];

  int B = in_sizes[0] / 784;
  int smem = (KV_U64 + ST_U64) * 8 + (int)sizeof(SW);
  cudaFuncSetAttribute(vit_kernel, cudaFuncAttributeMaxDynamicSharedMemorySize,
                       smem);
  dim3 grid((B + IPC - 1) / IPC);
  vit_kernel<<<grid, NTH, smem>>>(images, cls, linW, ln1g, ln1b, Wq, Wk, Wv,
                                  projW, projb, ln2g, ln2b, W1, b1, W2, b2,
                                  mlpW, mlpb, (float*)d_out, B);
}